// round 11
// baseline (speedup 1.0000x reference)
#include <cuda_runtime.h>
#include <math.h>

#define G   4          // batches per CTA
#define TS  16         // x_seq tile rows per buffer
#define NT  8          // tiles per batch (128/TS)
#define NHH 8
#define DD  512
#define SS  128
#define THREADS 512    // 16 warps

// SMEM float counts
#define BUF_F   (TS*DD)              // 8192 per buffer
#define XS_F    (2*BUF_F)            // 16384 (double buffer; also pass-2 partial scratch [4][8][512])
#define QTU_F   (G*NHH*DD)           // 16384  (qt, later reused as u)
#define QS_F    (G*DD)               // 2048
#define SC_F    (G*NHH*SS)           // 4096   (scores -> attn; also x_non staging)
#define QB_F    (G*NHH)              // 32
#define SMEM_F  (XS_F + QTU_F + QS_F + SC_F + QB_F)

typedef unsigned long long u64;
typedef ulonglong2 u64x2;

// packed f32x2 fused multiply-add: d = a*b + c elementwise on (lo,hi) pairs
__device__ __forceinline__ u64 ffma2(u64 a, u64 b, u64 c) {
    u64 d;
    asm("fma.rn.f32x2 %0, %1, %2, %3;" : "=l"(d) : "l"(a), "l"(b), "l"(c));
    return d;
}
__device__ __forceinline__ u64 fadd2(u64 a, u64 b) {
    u64 d;
    asm("add.rn.f32x2 %0, %1, %2;" : "=l"(d) : "l"(a), "l"(b));
    return d;
}
__device__ __forceinline__ u64 pack2(float lo, float hi) {
    u64 d; asm("mov.b64 %0, {%1, %2};" : "=l"(d) : "f"(lo), "f"(hi)); return d;
}
__device__ __forceinline__ float hsum2(u64 a) {
    float lo, hi;
    asm("mov.b64 {%0, %1}, %2;" : "=f"(lo), "=f"(hi) : "l"(a));
    return lo + hi;
}

__device__ __forceinline__ float warp_sum(float v) {
    v += __shfl_xor_sync(0xffffffffu, v, 16);
    v += __shfl_xor_sync(0xffffffffu, v, 8);
    v += __shfl_xor_sync(0xffffffffu, v, 4);
    v += __shfl_xor_sync(0xffffffffu, v, 2);
    v += __shfl_xor_sync(0xffffffffu, v, 1);
    return v;
}
__device__ __forceinline__ float warp_max(float v) {
    v = fmaxf(v, __shfl_xor_sync(0xffffffffu, v, 16));
    v = fmaxf(v, __shfl_xor_sync(0xffffffffu, v, 8));
    v = fmaxf(v, __shfl_xor_sync(0xffffffffu, v, 4));
    v = fmaxf(v, __shfl_xor_sync(0xffffffffu, v, 2));
    v = fmaxf(v, __shfl_xor_sync(0xffffffffu, v, 1));
    return v;
}

// 4 complete warp sums in 14 shuffles. Every lane returns total of value (lane&3).
__device__ __forceinline__ float reduce4(float a0, float a1, float a2, float a3, int lane) {
    a0 += __shfl_xor_sync(0xffffffffu, a0, 4);
    a1 += __shfl_xor_sync(0xffffffffu, a1, 4);
    a2 += __shfl_xor_sync(0xffffffffu, a2, 4);
    a3 += __shfl_xor_sync(0xffffffffu, a3, 4);
    a0 += __shfl_xor_sync(0xffffffffu, a0, 2);
    a1 += __shfl_xor_sync(0xffffffffu, a1, 2);
    a2 += __shfl_xor_sync(0xffffffffu, a2, 2);
    a3 += __shfl_xor_sync(0xffffffffu, a3, 2);
    a0 += __shfl_xor_sync(0xffffffffu, a0, 1);
    a1 += __shfl_xor_sync(0xffffffffu, a1, 1);
    a2 += __shfl_xor_sync(0xffffffffu, a2, 1);
    a3 += __shfl_xor_sync(0xffffffffu, a3, 1);
    float v = (lane & 2) ? ((lane & 1) ? a3 : a2) : ((lane & 1) ? a1 : a0);
    v += __shfl_xor_sync(0xffffffffu, v, 8);
    v += __shfl_xor_sync(0xffffffffu, v, 16);
    return v;
}

__device__ __forceinline__ void cp16(float4* dst_smem, const float4* src) {
    unsigned int d = (unsigned int)__cvta_generic_to_shared(dst_smem);
    asm volatile("cp.async.cg.shared.global [%0], [%1], 16;\n" :: "r"(d), "l"(src));
}
__device__ __forceinline__ void cp_commit() {
    asm volatile("cp.async.commit_group;\n" ::: "memory");
}
template <int N>
__device__ __forceinline__ void cp_wait() {
    asm volatile("cp.async.wait_group %0;\n" :: "n"(N) : "memory");
}

__global__ __launch_bounds__(THREADS, 1)
void mha_kernel(const float* __restrict__ x_non,
                const float* __restrict__ x_seq,
                const int*   __restrict__ mask,
                const float* __restrict__ Wq, const float* __restrict__ bq,
                const float* __restrict__ Wk, const float* __restrict__ bk,
                const float* __restrict__ Wv, const float* __restrict__ bv,
                float* __restrict__ out)
{
    extern __shared__ float smem[];
    float* xs  = smem;                 // 2 x [TS][512]; later [4][8][512] partial-u scratch
    float* qtu = xs + XS_F;            // [G][8][512]  qt then u
    float* qs  = qtu + QTU_F;          // [G][512]
    float* sc  = qs + QS_F;            // [G][8][128]  scores/attn (and x_non staging)
    float* qb  = sc + SC_F;            // [G][8]

    float4* xs4  = (float4*)xs;
    float4* qtu4 = (float4*)qtu;
    u64x2*  qtu2 = (u64x2*)qtu;

    const int tid  = threadIdx.x;
    const int lane = tid & 31;
    const int w    = tid >> 5;         // 0..15
    const int b0   = blockIdx.x * G;

    // shared mapping for BOTH attention passes: head quad + 2-row slice
    const int hq  = w >> 3;            // 0..1 -> heads hq*4 .. hq*4+3
    const int sl1 = w & 7;             // rows {sl1*2, sl1*2+1} of tile

    // ---- stage x_non[b0..b0+G) into sc region ----
    for (int i = tid; i < G*DD; i += THREADS)
        sc[i] = x_non[(size_t)b0*DD + i];
    __syncthreads();

    // ---- phase 1: q[g][i] = Wq[i,:]·xn[g] + bq[i]  (warp w -> rows [w*32, w*32+32)) ----
    {
        const u64x2* xn2 = (const u64x2*)sc;
        u64x2 xr[G][4];
        #pragma unroll
        for (int g = 0; g < G; g++)
            #pragma unroll
            for (int m = 0; m < 4; m++)
                xr[g][m] = xn2[g*128 + lane + 32*m];

        for (int r = 0; r < 32; r++) {
            const int i = w*32 + r;
            const u64x2* wrow = (const u64x2*)(Wq + (size_t)i*DD);
            u64 acc[G] = {0ull, 0ull, 0ull, 0ull};
            #pragma unroll
            for (int m = 0; m < 4; m++) {
                u64x2 wv = wrow[lane + 32*m];
                #pragma unroll
                for (int g = 0; g < G; g++) {
                    acc[g] = ffma2(wv.x, xr[g][m].x, acc[g]);
                    acc[g] = ffma2(wv.y, xr[g][m].y, acc[g]);
                }
            }
            float v = reduce4(hsum2(acc[0]), hsum2(acc[1]), hsum2(acc[2]), hsum2(acc[3]), lane);
            float bqi = __ldg(bq + i);
            if (lane < 4) qs[lane*DD + i] = v + bqi;
        }
    }
    __syncthreads();

    // ---- phase 2: qt[g][n][j] = sum_d Wk[n*64+d][j]·q[g][n*64+d] ; qb[g][n] = q·bk_n ----
    {
        for (int idx = tid; idx < NHH*128; idx += THREADS) {   // (n, j4)
            const int n  = idx >> 7;
            const int j4 = idx & 127;
            u64 acc[G][2];
            #pragma unroll
            for (int g = 0; g < G; g++) { acc[g][0] = 0ull; acc[g][1] = 0ull; }
            const u64x2* wk2 = (const u64x2*)Wk + (size_t)(n*64)*128 + j4;
            #pragma unroll 4
            for (int d = 0; d < 64; d++) {
                u64x2 wv = wk2[(size_t)d*128];
                #pragma unroll
                for (int g = 0; g < G; g++) {
                    float qv = qs[g*DD + n*64 + d];
                    u64 qp = pack2(qv, qv);
                    acc[g][0] = ffma2(wv.x, qp, acc[g][0]);
                    acc[g][1] = ffma2(wv.y, qp, acc[g][1]);
                }
            }
            #pragma unroll
            for (int g = 0; g < G; g++) {
                u64x2 t; t.x = acc[g][0]; t.y = acc[g][1];
                qtu2[g*1024 + idx] = t;
            }
        }
        if (tid < G*NHH) {
            const int gg = tid >> 3, n = tid & 7;
            float s = 0.f;
            for (int d = 0; d < 64; d++) s += qs[gg*DD + n*64 + d] * bk[n*64 + d];
            qb[tid] = s;
        }
    }
    __syncthreads();

    // ---- per-batch attention (two passes) ----
    for (int g = 0; g < G; g++) {
        const int b = b0 + g;
        const float4* xb4 = (const float4*)(x_seq + (size_t)b * SS * DD);  // 2048 float4/tile

        // hoist qt lane slices for this warp's 4 heads, packed
        u64x2 qtr[4][4];
        #pragma unroll
        for (int h = 0; h < 4; h++)
            #pragma unroll
            for (int m = 0; m < 4; m++)
                qtr[h][m] = qtu2[g*1024 + (hq*4+h)*128 + lane + 32*m];

        // prime tile 0 into buf0
        {
            #pragma unroll
            for (int i = 0; i < 4; i++) cp16(&xs4[tid + 512*i], &xb4[tid + 512*i]);
            cp_commit();
        }

        // ---- pass 1: raw scores (bias added in softmax) ----
        for (int t = 0; t < NT; t++) {
            __syncthreads();   // everyone done with buf[(t+1)&1]'s old contents
            if (t + 1 < NT) {
                float4* dst = xs4 + ((t+1)&1)*2048;
                const float4* src = xb4 + (size_t)(t+1)*2048;
                #pragma unroll
                for (int i = 0; i < 4; i++) cp16(&dst[tid + 512*i], &src[tid + 512*i]);
                cp_commit();
                cp_wait<1>();
            } else {
                cp_wait<0>();
            }
            __syncthreads();   // tile t visible to all

            const float* buf = xs + (t&1)*BUF_F;
            #pragma unroll 2
            for (int r = 0; r < 2; r++) {
                const int srow = sl1*2 + r;
                const u64x2* xr = (const u64x2*)(buf + srow*DD);
                u64 a0 = 0ull, a1 = 0ull, a2 = 0ull, a3 = 0ull;
                #pragma unroll
                for (int m = 0; m < 4; m++) {
                    u64x2 xv = xr[lane + 32*m];
                    a0 = ffma2(xv.x, qtr[0][m].x, a0);
                    a0 = ffma2(xv.y, qtr[0][m].y, a0);
                    a1 = ffma2(xv.x, qtr[1][m].x, a1);
                    a1 = ffma2(xv.y, qtr[1][m].y, a1);
                    a2 = ffma2(xv.x, qtr[2][m].x, a2);
                    a2 = ffma2(xv.y, qtr[2][m].y, a2);
                    a3 = ffma2(xv.x, qtr[3][m].x, a3);
                    a3 = ffma2(xv.y, qtr[3][m].y, a3);
                }
                float v = reduce4(hsum2(a0), hsum2(a1), hsum2(a2), hsum2(a3), lane);
                if (lane < 4) {
                    const int s = t*TS + srow;
                    sc[g*1024 + (hq*4 + lane)*SS + s] = v;
                }
            }
        }
        __syncthreads();

        // ---- softmax (warps 0..7, warp w -> head w) ----
        if (w < NHH) {
            const int* mrow = mask + ((size_t)b*NHH + w)*SS;
            const float qbb = qb[g*NHH + w];
            float l[4];
            #pragma unroll
            for (int k = 0; k < 4; k++) {
                const int s = lane + 32*k;
                float raw = sc[g*1024 + w*SS + s] + qbb;
                l[k] = (mrow[s] != 0) ? floorf(raw * 0.125f) : -1e30f;
            }
            float mx = fmaxf(fmaxf(l[0],l[1]), fmaxf(l[2],l[3]));
            mx = warp_max(mx);
            float e[4]; float ssum = 0.f;
            #pragma unroll
            for (int k = 0; k < 4; k++) { e[k] = __expf(l[k] - mx); ssum += e[k]; }
            ssum = warp_sum(ssum);
            const float inv = 1.0f / ssum;
            #pragma unroll
            for (int k = 0; k < 4; k++)
                sc[g*1024 + w*SS + lane + 32*k] = e[k] * inv;
        }
        __syncthreads();

        // ---- pass 2 (same (hq, sl1) mapping: 4 heads x 2 rows; reverse tiles, 7/6 resident) ----
        {
            u64 ua[4][8];   // 4 heads x 16 floats (8 u64) per lane
            #pragma unroll
            for (int h = 0; h < 4; h++)
                #pragma unroll
                for (int m = 0; m < 8; m++) ua[h][m] = 0ull;

            for (int t = NT-1; t >= 0; t--) {
                if (t <= NT-3) {              // prefetched tile: wait for it
                    if (t > 0) cp_wait<1>(); else cp_wait<0>();
                    __syncthreads();
                }
                const float* buf = xs + (t&1)*BUF_F;
                #pragma unroll
                for (int r = 0; r < 2; r++) {
                    const int srow = sl1*2 + r;
                    u64 wp[4];
                    #pragma unroll
                    for (int h = 0; h < 4; h++) {
                        float ws = sc[g*1024 + (hq*4+h)*SS + t*TS + srow];
                        wp[h] = pack2(ws, ws);
                    }
                    const u64x2* xr = (const u64x2*)(buf + srow*DD);
                    #pragma unroll
                    for (int m = 0; m < 4; m++) {
                        u64x2 xv = xr[lane + 32*m];
                        #pragma unroll
                        for (int h = 0; h < 4; h++) {
                            ua[h][2*m+0] = ffma2(wp[h], xv.x, ua[h][2*m+0]);
                            ua[h][2*m+1] = ffma2(wp[h], xv.y, ua[h][2*m+1]);
                        }
                    }
                }
                __syncthreads();    // done reading buf[t&1]
                if (t - 2 >= 0) {   // prefetch tile t-2 into the buffer just freed
                    float4* dst = xs4 + (t&1)*2048;
                    const float4* src = xb4 + (size_t)(t-2)*2048;
                    #pragma unroll
                    for (int i = 0; i < 4; i++) cp16(&dst[tid + 512*i], &src[tid + 512*i]);
                    cp_commit();
                }
            }

            // ---- two-round slice combine in 16K scratch [4][8][512] ----
            u64x2* xs2 = (u64x2*)xs;
            // round 1: slices 4..7 dump into scratch slot [(sl1-4)*8 + head]
            if (sl1 >= 4) {
                #pragma unroll
                for (int h = 0; h < 4; h++) {
                    #pragma unroll
                    for (int m = 0; m < 4; m++) {
                        u64x2 t0; t0.x = ua[h][2*m+0]; t0.y = ua[h][2*m+1];
                        xs2[((sl1-4)*8 + hq*4+h)*128 + lane + 32*m] = t0;
                    }
                }
            }
            __syncthreads();
            // round 2: slices 0..3 add matching slot into registers, write combined back
            if (sl1 < 4) {
                #pragma unroll
                for (int h = 0; h < 4; h++) {
                    #pragma unroll
                    for (int m = 0; m < 4; m++) {
                        const int slot = (sl1*8 + hq*4+h)*128 + lane + 32*m;
                        u64x2 pv = xs2[slot];
                        u64x2 t0;
                        t0.x = fadd2(ua[h][2*m+0], pv.x);
                        t0.y = fadd2(ua[h][2*m+1], pv.y);
                        xs2[slot] = t0;      // same slot: touched by this warp only
                    }
                }
            }
            __syncthreads();
            // final: sum the 4 combined slices -> u in qtu[g]
            for (int idx = tid; idx < NHH*128; idx += THREADS) {
                float4 s0 = xs4[0*1024 + idx];
                float4 s1 = xs4[1*1024 + idx];
                float4 s2 = xs4[2*1024 + idx];
                float4 s3 = xs4[3*1024 + idx];
                float4 r;
                r.x = (s0.x + s1.x) + (s2.x + s3.x);
                r.y = (s0.y + s1.y) + (s2.y + s3.y);
                r.z = (s0.z + s1.z) + (s2.z + s3.z);
                r.w = (s0.w + s1.w) + (s2.w + s3.w);
                qtu4[g*1024 + idx] = r;
            }
            __syncthreads();   // scratch consumed before next batch's priming
        }
    } // batches

    // ---- phase z: out[b_g][i] = Wv[i,:]·u[g][head(i)] + bv[i]  (warp w -> rows [w*32, w*32+32)) ----
    {
        const int zn = w >> 1;   // head for this warp's rows
        u64x2 ur[G][4];
        #pragma unroll
        for (int g = 0; g < G; g++)
            #pragma unroll
            for (int m = 0; m < 4; m++)
                ur[g][m] = qtu2[g*1024 + zn*128 + lane + 32*m];

        for (int r = 0; r < 32; r++) {
            const int i = w*32 + r;
            const u64x2* wrow = (const u64x2*)(Wv + (size_t)i*DD);
            u64 acc[G] = {0ull, 0ull, 0ull, 0ull};
            #pragma unroll
            for (int m = 0; m < 4; m++) {
                u64x2 wv = wrow[lane + 32*m];
                #pragma unroll
                for (int g = 0; g < G; g++) {
                    acc[g] = ffma2(wv.x, ur[g][m].x, acc[g]);
                    acc[g] = ffma2(wv.y, ur[g][m].y, acc[g]);
                }
            }
            float v = reduce4(hsum2(acc[0]), hsum2(acc[1]), hsum2(acc[2]), hsum2(acc[3]), lane);
            float bvi = __ldg(bv + i);
            if (lane < 4)
                out[(size_t)(b0 + lane)*DD + i] = v + bvi;
        }
    }
}

extern "C" void kernel_launch(void* const* d_in, const int* in_sizes, int n_in,
                              void* d_out, int out_size)
{
    const float* x_non = (const float*)d_in[0];
    const float* x_seq = (const float*)d_in[1];
    const int*   mask  = (const int*)  d_in[2];
    const float* Wq    = (const float*)d_in[3];
    const float* bq    = (const float*)d_in[4];
    const float* Wk    = (const float*)d_in[5];
    const float* bk    = (const float*)d_in[6];
    const float* Wv    = (const float*)d_in[7];
    const float* bv    = (const float*)d_in[8];
    float* out = (float*)d_out;

    const int smem_bytes = SMEM_F * (int)sizeof(float);   // ~152 KB
    cudaFuncSetAttribute(mha_kernel, cudaFuncAttributeMaxDynamicSharedMemorySize, smem_bytes);
    mha_kernel<<<1024/G, THREADS, smem_bytes>>>(x_non, x_seq, mask,
                                                Wq, bq, Wk, bk, Wv, bv, out);
}

// round 12
// speedup vs baseline: 1.4695x; 1.4695x over previous
#include <cuda_runtime.h>
#include <math.h>

#define G   4          // batches per CTA
#define TS  32         // x_seq tile rows per buffer
#define NT  4          // tiles per batch (128/TS)
#define NHH 8
#define DD  512
#define SS  128
#define THREADS 512    // 16 warps

// SMEM float counts
#define BUF_F   (TS*DD)              // 16384 per buffer
#define XS_F    (2*BUF_F)            // 32768 (double buffer; also pass-2 partial scratch [4][8][512])
#define QTU_F   (G*NHH*DD)           // 16384  (qt, later reused as u)
#define QS_F    (G*DD)               // 2048
#define SC_F    (G*NHH*SS)           // 4096   (scores -> attn; also x_non staging)
#define QB_F    (G*NHH)              // 32
#define SMEM_F  (XS_F + QTU_F + QS_F + SC_F + QB_F)   // 55328 fl ~216 KB

typedef unsigned long long u64;
typedef ulonglong2 u64x2;

// packed f32x2 fused multiply-add: d = a*b + c elementwise on (lo,hi) pairs
__device__ __forceinline__ u64 ffma2(u64 a, u64 b, u64 c) {
    u64 d;
    asm("fma.rn.f32x2 %0, %1, %2, %3;" : "=l"(d) : "l"(a), "l"(b), "l"(c));
    return d;
}
__device__ __forceinline__ u64 pack2(float lo, float hi) {
    u64 d; asm("mov.b64 %0, {%1, %2};" : "=l"(d) : "f"(lo), "f"(hi)); return d;
}
__device__ __forceinline__ float hsum2(u64 a) {
    float lo, hi;
    asm("mov.b64 {%0, %1}, %2;" : "=f"(lo), "=f"(hi) : "l"(a));
    return lo + hi;
}

__device__ __forceinline__ float warp_sum(float v) {
    v += __shfl_xor_sync(0xffffffffu, v, 16);
    v += __shfl_xor_sync(0xffffffffu, v, 8);
    v += __shfl_xor_sync(0xffffffffu, v, 4);
    v += __shfl_xor_sync(0xffffffffu, v, 2);
    v += __shfl_xor_sync(0xffffffffu, v, 1);
    return v;
}
__device__ __forceinline__ float warp_max(float v) {
    v = fmaxf(v, __shfl_xor_sync(0xffffffffu, v, 16));
    v = fmaxf(v, __shfl_xor_sync(0xffffffffu, v, 8));
    v = fmaxf(v, __shfl_xor_sync(0xffffffffu, v, 4));
    v = fmaxf(v, __shfl_xor_sync(0xffffffffu, v, 2));
    v = fmaxf(v, __shfl_xor_sync(0xffffffffu, v, 1));
    return v;
}

// 4 complete warp sums in 14 shuffles. Every lane returns total of value (lane&3).
__device__ __forceinline__ float reduce4(float a0, float a1, float a2, float a3, int lane) {
    a0 += __shfl_xor_sync(0xffffffffu, a0, 4);
    a1 += __shfl_xor_sync(0xffffffffu, a1, 4);
    a2 += __shfl_xor_sync(0xffffffffu, a2, 4);
    a3 += __shfl_xor_sync(0xffffffffu, a3, 4);
    a0 += __shfl_xor_sync(0xffffffffu, a0, 2);
    a1 += __shfl_xor_sync(0xffffffffu, a1, 2);
    a2 += __shfl_xor_sync(0xffffffffu, a2, 2);
    a3 += __shfl_xor_sync(0xffffffffu, a3, 2);
    a0 += __shfl_xor_sync(0xffffffffu, a0, 1);
    a1 += __shfl_xor_sync(0xffffffffu, a1, 1);
    a2 += __shfl_xor_sync(0xffffffffu, a2, 1);
    a3 += __shfl_xor_sync(0xffffffffu, a3, 1);
    float v = (lane & 2) ? ((lane & 1) ? a3 : a2) : ((lane & 1) ? a1 : a0);
    v += __shfl_xor_sync(0xffffffffu, v, 8);
    v += __shfl_xor_sync(0xffffffffu, v, 16);
    return v;
}

__device__ __forceinline__ void cp16(float4* dst_smem, const float4* src) {
    unsigned int d = (unsigned int)__cvta_generic_to_shared(dst_smem);
    asm volatile("cp.async.cg.shared.global [%0], [%1], 16;\n" :: "r"(d), "l"(src));
}
__device__ __forceinline__ void cp_commit() {
    asm volatile("cp.async.commit_group;\n" ::: "memory");
}
template <int N>
__device__ __forceinline__ void cp_wait() {
    asm volatile("cp.async.wait_group %0;\n" :: "n"(N) : "memory");
}

__global__ __launch_bounds__(THREADS, 1)
void mha_kernel(const float* __restrict__ x_non,
                const float* __restrict__ x_seq,
                const int*   __restrict__ mask,
                const float* __restrict__ Wq, const float* __restrict__ bq,
                const float* __restrict__ Wk, const float* __restrict__ bk,
                const float* __restrict__ Wv, const float* __restrict__ bv,
                float* __restrict__ out)
{
    extern __shared__ float smem[];
    float* xs  = smem;                 // 2 x [TS][512]; later [4][8][512] partial-u scratch
    float* qtu = xs + XS_F;            // [G][8][512]  qt then u
    float* qs  = qtu + QTU_F;          // [G][512]
    float* sc  = qs + QS_F;            // [G][8][128]  scores/attn (and x_non staging)
    float* qb  = sc + SC_F;            // [G][8]

    float4* xs4  = (float4*)xs;
    float4* qtu4 = (float4*)qtu;
    u64x2*  qtu2 = (u64x2*)qtu;

    const int tid  = threadIdx.x;
    const int lane = tid & 31;
    const int w    = tid >> 5;         // 0..15
    const int b0   = blockIdx.x * G;

    // pass-1 mapping: head quad + 4-row slice
    const int hq  = w >> 3;            // 0..1 -> heads hq*4 .. hq*4+3
    const int sl1 = w & 7;             // rows [sl1*4, sl1*4+4) of 32-row tile
    // pass-2 mapping: head pair + 8-row slice
    const int hp  = w >> 2;            // 0..3 -> heads hp*2, hp*2+1
    const int sl2 = w & 3;             // rows [sl2*8, sl2*8+8) of tile

    // ---- stage x_non[b0..b0+G) into sc region ----
    for (int i = tid; i < G*DD; i += THREADS)
        sc[i] = x_non[(size_t)b0*DD + i];
    __syncthreads();

    // ---- phase 1: q[g][i] = Wq[i,:]·xn[g] + bq[i]  (warp w -> rows [w*32, w*32+32)) ----
    {
        const u64x2* xn2 = (const u64x2*)sc;
        u64x2 xr[G][4];
        #pragma unroll
        for (int g = 0; g < G; g++)
            #pragma unroll
            for (int m = 0; m < 4; m++)
                xr[g][m] = xn2[g*128 + lane + 32*m];

        for (int r = 0; r < 32; r++) {
            const int i = w*32 + r;
            const u64x2* wrow = (const u64x2*)(Wq + (size_t)i*DD);
            u64 acc[G] = {0ull, 0ull, 0ull, 0ull};
            #pragma unroll
            for (int m = 0; m < 4; m++) {
                u64x2 wv = wrow[lane + 32*m];
                #pragma unroll
                for (int g = 0; g < G; g++) {
                    acc[g] = ffma2(wv.x, xr[g][m].x, acc[g]);
                    acc[g] = ffma2(wv.y, xr[g][m].y, acc[g]);
                }
            }
            float v = reduce4(hsum2(acc[0]), hsum2(acc[1]), hsum2(acc[2]), hsum2(acc[3]), lane);
            float bqi = __ldg(bq + i);
            if (lane < 4) qs[lane*DD + i] = v + bqi;
        }
    }
    __syncthreads();

    // ---- phase 2: qt[g][n][j] = sum_d Wk[n*64+d][j]·q[g][n*64+d] ; qb[g][n] = q·bk_n ----
    {
        for (int idx = tid; idx < NHH*128; idx += THREADS) {   // (n, j4)
            const int n  = idx >> 7;
            const int j4 = idx & 127;
            u64 acc[G][2];
            #pragma unroll
            for (int g = 0; g < G; g++) { acc[g][0] = 0ull; acc[g][1] = 0ull; }
            const u64x2* wk2 = (const u64x2*)Wk + (size_t)(n*64)*128 + j4;
            #pragma unroll 4
            for (int d = 0; d < 64; d++) {
                u64x2 wv = wk2[(size_t)d*128];
                #pragma unroll
                for (int g = 0; g < G; g++) {
                    float qv = qs[g*DD + n*64 + d];
                    u64 qp = pack2(qv, qv);
                    acc[g][0] = ffma2(wv.x, qp, acc[g][0]);
                    acc[g][1] = ffma2(wv.y, qp, acc[g][1]);
                }
            }
            #pragma unroll
            for (int g = 0; g < G; g++) {
                u64x2 t; t.x = acc[g][0]; t.y = acc[g][1];
                qtu2[g*1024 + idx] = t;
            }
        }
        if (tid < G*NHH) {
            const int gg = tid >> 3, n = tid & 7;
            float s = 0.f;
            for (int d = 0; d < 64; d++) s += qs[gg*DD + n*64 + d] * bk[n*64 + d];
            qb[tid] = s;
        }
    }
    __syncthreads();

    // ---- per-batch attention (two passes) ----
    for (int g = 0; g < G; g++) {
        const int b = b0 + g;
        const float4* xb4 = (const float4*)(x_seq + (size_t)b * SS * DD);  // 4096 float4/tile

        // hoist qt lane slices for this warp's 4 heads (pass-1), packed
        u64x2 qtr[4][4];
        #pragma unroll
        for (int h = 0; h < 4; h++)
            #pragma unroll
            for (int m = 0; m < 4; m++)
                qtr[h][m] = qtu2[g*1024 + (hq*4+h)*128 + lane + 32*m];

        // prime tile 0 into buf0
        {
            #pragma unroll
            for (int i = 0; i < 8; i++) cp16(&xs4[tid + 512*i], &xb4[tid + 512*i]);
            cp_commit();
        }

        // ---- pass 1: raw scores (bias added in softmax) ----
        for (int t = 0; t < NT; t++) {
            __syncthreads();   // everyone done with buf[(t+1)&1]'s old contents
            if (t + 1 < NT) {
                float4* dst = xs4 + ((t+1)&1)*4096;
                const float4* src = xb4 + (size_t)(t+1)*4096;
                #pragma unroll
                for (int i = 0; i < 8; i++) cp16(&dst[tid + 512*i], &src[tid + 512*i]);
                cp_commit();
                cp_wait<1>();
            } else {
                cp_wait<0>();
            }
            __syncthreads();   // tile t visible to all

            const float* buf = xs + (t&1)*BUF_F;
            #pragma unroll 2
            for (int r = 0; r < 4; r++) {
                const int srow = sl1*4 + r;
                const u64x2* xr = (const u64x2*)(buf + srow*DD);
                u64 a0 = 0ull, a1 = 0ull, a2 = 0ull, a3 = 0ull;
                #pragma unroll
                for (int m = 0; m < 4; m++) {
                    u64x2 xv = xr[lane + 32*m];
                    a0 = ffma2(xv.x, qtr[0][m].x, a0);
                    a0 = ffma2(xv.y, qtr[0][m].y, a0);
                    a1 = ffma2(xv.x, qtr[1][m].x, a1);
                    a1 = ffma2(xv.y, qtr[1][m].y, a1);
                    a2 = ffma2(xv.x, qtr[2][m].x, a2);
                    a2 = ffma2(xv.y, qtr[2][m].y, a2);
                    a3 = ffma2(xv.x, qtr[3][m].x, a3);
                    a3 = ffma2(xv.y, qtr[3][m].y, a3);
                }
                float v = reduce4(hsum2(a0), hsum2(a1), hsum2(a2), hsum2(a3), lane);
                if (lane < 4) {
                    const int s = t*TS + srow;
                    sc[g*1024 + (hq*4 + lane)*SS + s] = v;
                }
            }
        }
        __syncthreads();

        // ---- softmax (warps 0..7, warp w -> head w) ----
        if (w < NHH) {
            const int* mrow = mask + ((size_t)b*NHH + w)*SS;
            const float qbb = qb[g*NHH + w];
            float l[4];
            #pragma unroll
            for (int k = 0; k < 4; k++) {
                const int s = lane + 32*k;
                float raw = sc[g*1024 + w*SS + s] + qbb;
                l[k] = (mrow[s] != 0) ? floorf(raw * 0.125f) : -1e30f;
            }
            float mx = fmaxf(fmaxf(l[0],l[1]), fmaxf(l[2],l[3]));
            mx = warp_max(mx);
            float e[4]; float ssum = 0.f;
            #pragma unroll
            for (int k = 0; k < 4; k++) { e[k] = __expf(l[k] - mx); ssum += e[k]; }
            ssum = warp_sum(ssum);
            const float inv = 1.0f / ssum;
            #pragma unroll
            for (int k = 0; k < 4; k++)
                sc[g*1024 + w*SS + lane + 32*k] = e[k] * inv;
        }
        __syncthreads();

        // ---- pass 2 (reverse tiles; 3 and 2 still resident from pass 1) ----
        {
            const int h0 = hp*2;
            u64 ua0[8], ua1[8];
            #pragma unroll
            for (int m = 0; m < 8; m++) { ua0[m] = 0ull; ua1[m] = 0ull; }

            for (int t = NT-1; t >= 0; t--) {
                if (t <= NT-3) {              // prefetched tile: wait for it
                    if (t > 0) cp_wait<1>(); else cp_wait<0>();
                    __syncthreads();
                }
                const float* buf = xs + (t&1)*BUF_F;
                #pragma unroll 2
                for (int r = 0; r < 8; r++) {
                    const int srow = sl2*8 + r;
                    const float w0s = sc[g*1024 + (h0+0)*SS + t*TS + srow];
                    const float w1s = sc[g*1024 + (h0+1)*SS + t*TS + srow];
                    const u64 w0p = pack2(w0s, w0s);
                    const u64 w1p = pack2(w1s, w1s);
                    const u64x2* xr = (const u64x2*)(buf + srow*DD);
                    #pragma unroll
                    for (int m = 0; m < 4; m++) {
                        u64x2 xv = xr[lane + 32*m];
                        ua0[2*m+0] = ffma2(w0p, xv.x, ua0[2*m+0]);
                        ua0[2*m+1] = ffma2(w0p, xv.y, ua0[2*m+1]);
                        ua1[2*m+0] = ffma2(w1p, xv.x, ua1[2*m+0]);
                        ua1[2*m+1] = ffma2(w1p, xv.y, ua1[2*m+1]);
                    }
                }
                __syncthreads();    // done reading buf[t&1]
                if (t - 2 >= 0) {   // prefetch tile t-2 into the buffer just freed
                    float4* dst = xs4 + (t&1)*4096;
                    const float4* src = xb4 + (size_t)(t-2)*4096;
                    #pragma unroll
                    for (int i = 0; i < 8; i++) cp16(&dst[tid + 512*i], &src[tid + 512*i]);
                    cp_commit();
                }
            }

            // dump partials into xs scratch: [sl2][head][512]  (16K floats; xs holds 32K)
            u64x2* xs2 = (u64x2*)xs;
            #pragma unroll
            for (int m = 0; m < 4; m++) {
                u64x2 t0; t0.x = ua0[2*m+0]; t0.y = ua0[2*m+1];
                u64x2 t1; t1.x = ua1[2*m+0]; t1.y = ua1[2*m+1];
                xs2[(sl2*8 + h0+0)*128 + lane + 32*m] = t0;
                xs2[(sl2*8 + h0+1)*128 + lane + 32*m] = t1;
            }
            __syncthreads();
            // reduce across the 4 s-slices -> u in qtu[g]
            for (int idx = tid; idx < NHH*128; idx += THREADS) {
                float4 s0 = xs4[0*1024 + idx];
                float4 s1 = xs4[1*1024 + idx];
                float4 s2 = xs4[2*1024 + idx];
                float4 s3 = xs4[3*1024 + idx];
                float4 r;
                r.x = (s0.x + s1.x) + (s2.x + s3.x);
                r.y = (s0.y + s1.y) + (s2.y + s3.y);
                r.z = (s0.z + s1.z) + (s2.z + s3.z);
                r.w = (s0.w + s1.w) + (s2.w + s3.w);
                qtu4[g*1024 + idx] = r;
            }
            __syncthreads();   // scratch consumed before next batch's priming
        }
    } // batches

    // ---- phase z: out[b_g][i] = Wv[i,:]·u[g][head(i)] + bv[i]  (warp w -> rows [w*32, w*32+32)) ----
    {
        const int zn = w >> 1;   // head for this warp's rows
        u64x2 ur[G][4];
        #pragma unroll
        for (int g = 0; g < G; g++)
            #pragma unroll
            for (int m = 0; m < 4; m++)
                ur[g][m] = qtu2[g*1024 + zn*128 + lane + 32*m];

        for (int r = 0; r < 32; r++) {
            const int i = w*32 + r;
            const u64x2* wrow = (const u64x2*)(Wv + (size_t)i*DD);
            u64 acc[G] = {0ull, 0ull, 0ull, 0ull};
            #pragma unroll
            for (int m = 0; m < 4; m++) {
                u64x2 wv = wrow[lane + 32*m];
                #pragma unroll
                for (int g = 0; g < G; g++) {
                    acc[g] = ffma2(wv.x, ur[g][m].x, acc[g]);
                    acc[g] = ffma2(wv.y, ur[g][m].y, acc[g]);
                }
            }
            float v = reduce4(hsum2(acc[0]), hsum2(acc[1]), hsum2(acc[2]), hsum2(acc[3]), lane);
            float bvi = __ldg(bv + i);
            if (lane < 4)
                out[(size_t)(b0 + lane)*DD + i] = v + bvi;
        }
    }
}

extern "C" void kernel_launch(void* const* d_in, const int* in_sizes, int n_in,
                              void* d_out, int out_size)
{
    const float* x_non = (const float*)d_in[0];
    const float* x_seq = (const float*)d_in[1];
    const int*   mask  = (const int*)  d_in[2];
    const float* Wq    = (const float*)d_in[3];
    const float* bq    = (const float*)d_in[4];
    const float* Wk    = (const float*)d_in[5];
    const float* bk    = (const float*)d_in[6];
    const float* Wv    = (const float*)d_in[7];
    const float* bv    = (const float*)d_in[8];
    float* out = (float*)d_out;

    const int smem_bytes = SMEM_F * (int)sizeof(float);   // ~216 KB
    cudaFuncSetAttribute(mha_kernel, cudaFuncAttributeMaxDynamicSharedMemorySize, smem_bytes);
    mha_kernel<<<1024/G, THREADS, smem_bytes>>>(x_non, x_seq, mask,
                                                Wq, bq, Wk, bk, Wv, bv, out);
}

// round 13
// speedup vs baseline: 1.5344x; 1.0442x over previous
#include <cuda_runtime.h>
#include <math.h>

#define G   4          // batches per CTA
#define TS  32         // x_seq tile rows per buffer
#define NT  4          // tiles per batch (128/TS)
#define NHH 8
#define DD  512
#define SS  128
#define THREADS 512    // 16 warps

// SMEM float counts
#define BUF_F   (TS*DD)              // 16384 per buffer
#define XS_F    (2*BUF_F)            // 32768 (double buffer; also pass-2 partial scratch [4][8][512])
#define QTU_F   (G*NHH*DD)           // 16384  (qt, later reused as u)
#define QS_F    (G*DD)               // 2048
#define SC_F    (G*NHH*SS)           // 4096   (scores -> attn; also x_non staging)
#define QB_F    (G*NHH)              // 32
#define SMEM_F  (XS_F + QTU_F + QS_F + SC_F + QB_F)   // ~216 KB

typedef unsigned long long u64;
typedef ulonglong2 u64x2;

// packed f32x2 fused multiply-add: d = a*b + c elementwise on (lo,hi) pairs
__device__ __forceinline__ u64 ffma2(u64 a, u64 b, u64 c) {
    u64 d;
    asm("fma.rn.f32x2 %0, %1, %2, %3;" : "=l"(d) : "l"(a), "l"(b), "l"(c));
    return d;
}
__device__ __forceinline__ u64 pack2(float lo, float hi) {
    u64 d; asm("mov.b64 %0, {%1, %2};" : "=l"(d) : "f"(lo), "f"(hi)); return d;
}
__device__ __forceinline__ float hsum2(u64 a) {
    float lo, hi;
    asm("mov.b64 {%0, %1}, %2;" : "=f"(lo), "=f"(hi) : "l"(a));
    return lo + hi;
}

__device__ __forceinline__ float warp_sum(float v) {
    v += __shfl_xor_sync(0xffffffffu, v, 16);
    v += __shfl_xor_sync(0xffffffffu, v, 8);
    v += __shfl_xor_sync(0xffffffffu, v, 4);
    v += __shfl_xor_sync(0xffffffffu, v, 2);
    v += __shfl_xor_sync(0xffffffffu, v, 1);
    return v;
}
__device__ __forceinline__ float warp_max(float v) {
    v = fmaxf(v, __shfl_xor_sync(0xffffffffu, v, 16));
    v = fmaxf(v, __shfl_xor_sync(0xffffffffu, v, 8));
    v = fmaxf(v, __shfl_xor_sync(0xffffffffu, v, 4));
    v = fmaxf(v, __shfl_xor_sync(0xffffffffu, v, 2));
    v = fmaxf(v, __shfl_xor_sync(0xffffffffu, v, 1));
    return v;
}

// 8 complete warp sums in 26 shuffles, single depth-5 chain.
// Every lane returns total of value (lane&7); lanes 0..7 together hold all 8.
__device__ __forceinline__ float reduce8(float a0, float a1, float a2, float a3,
                                         float a4, float a5, float a6, float a7,
                                         int lane) {
    a0 += __shfl_xor_sync(0xffffffffu, a0, 4);
    a1 += __shfl_xor_sync(0xffffffffu, a1, 4);
    a2 += __shfl_xor_sync(0xffffffffu, a2, 4);
    a3 += __shfl_xor_sync(0xffffffffu, a3, 4);
    a4 += __shfl_xor_sync(0xffffffffu, a4, 4);
    a5 += __shfl_xor_sync(0xffffffffu, a5, 4);
    a6 += __shfl_xor_sync(0xffffffffu, a6, 4);
    a7 += __shfl_xor_sync(0xffffffffu, a7, 4);
    a0 += __shfl_xor_sync(0xffffffffu, a0, 2);
    a1 += __shfl_xor_sync(0xffffffffu, a1, 2);
    a2 += __shfl_xor_sync(0xffffffffu, a2, 2);
    a3 += __shfl_xor_sync(0xffffffffu, a3, 2);
    a4 += __shfl_xor_sync(0xffffffffu, a4, 2);
    a5 += __shfl_xor_sync(0xffffffffu, a5, 2);
    a6 += __shfl_xor_sync(0xffffffffu, a6, 2);
    a7 += __shfl_xor_sync(0xffffffffu, a7, 2);
    a0 += __shfl_xor_sync(0xffffffffu, a0, 1);
    a1 += __shfl_xor_sync(0xffffffffu, a1, 1);
    a2 += __shfl_xor_sync(0xffffffffu, a2, 1);
    a3 += __shfl_xor_sync(0xffffffffu, a3, 1);
    a4 += __shfl_xor_sync(0xffffffffu, a4, 1);
    a5 += __shfl_xor_sync(0xffffffffu, a5, 1);
    a6 += __shfl_xor_sync(0xffffffffu, a6, 1);
    a7 += __shfl_xor_sync(0xffffffffu, a7, 1);
    // lane l now holds the partial of its aligned-8 group (l>>3) for all 8 values
    float v = (lane & 4) ? ((lane & 2) ? ((lane & 1) ? a7 : a6) : ((lane & 1) ? a5 : a4))
                         : ((lane & 2) ? ((lane & 1) ? a3 : a2) : ((lane & 1) ? a1 : a0));
    v += __shfl_xor_sync(0xffffffffu, v, 8);
    v += __shfl_xor_sync(0xffffffffu, v, 16);
    return v;
}

__device__ __forceinline__ void cp16(float4* dst_smem, const float4* src) {
    unsigned int d = (unsigned int)__cvta_generic_to_shared(dst_smem);
    asm volatile("cp.async.cg.shared.global [%0], [%1], 16;\n" :: "r"(d), "l"(src));
}
__device__ __forceinline__ void cp_commit() {
    asm volatile("cp.async.commit_group;\n" ::: "memory");
}
template <int N>
__device__ __forceinline__ void cp_wait() {
    asm volatile("cp.async.wait_group %0;\n" :: "n"(N) : "memory");
}

__global__ __launch_bounds__(THREADS, 1)
void mha_kernel(const float* __restrict__ x_non,
                const float* __restrict__ x_seq,
                const int*   __restrict__ mask,
                const float* __restrict__ Wq, const float* __restrict__ bq,
                const float* __restrict__ Wk, const float* __restrict__ bk,
                const float* __restrict__ Wv, const float* __restrict__ bv,
                float* __restrict__ out)
{
    extern __shared__ float smem[];
    float* xs  = smem;                 // 2 x [TS][512]; later [4][8][512] partial-u scratch
    float* qtu = xs + XS_F;            // [G][8][512]  qt then u
    float* qs  = qtu + QTU_F;          // [G][512]
    float* sc  = qs + QS_F;            // [G][8][128]  scores/attn (and x_non staging)
    float* qb  = sc + SC_F;            // [G][8]

    float4* xs4  = (float4*)xs;
    float4* qtu4 = (float4*)qtu;
    u64x2*  qtu2 = (u64x2*)qtu;

    const int tid  = threadIdx.x;
    const int lane = tid & 31;
    const int w    = tid >> 5;         // 0..15
    const int b0   = blockIdx.x * G;

    // pass-1 mapping: head quad + 4-row slice
    const int hq  = w >> 3;            // 0..1 -> heads hq*4 .. hq*4+3
    const int sl1 = w & 7;             // rows [sl1*4, sl1*4+4) of 32-row tile
    // pass-2 mapping: head pair + 8-row slice
    const int hp  = w >> 2;            // 0..3 -> heads hp*2, hp*2+1
    const int sl2 = w & 3;             // rows [sl2*8, sl2*8+8) of tile

    // ---- stage x_non[b0..b0+G) into sc region ----
    for (int i = tid; i < G*DD; i += THREADS)
        sc[i] = x_non[(size_t)b0*DD + i];
    __syncthreads();

    // ---- phase 1: q[g][i] = Wq[i,:]·xn[g] + bq[i]  (warp w -> rows [w*32, w*32+32), 2 at a time) ----
    {
        const u64x2* xn2 = (const u64x2*)sc;
        u64x2 xr[G][4];
        #pragma unroll
        for (int g = 0; g < G; g++)
            #pragma unroll
            for (int m = 0; m < 4; m++)
                xr[g][m] = xn2[g*128 + lane + 32*m];

        for (int rr = 0; rr < 32; rr += 2) {
            const int i = w*32 + rr;
            const u64x2* wrow0 = (const u64x2*)(Wq + (size_t)i*DD);
            const u64x2* wrow1 = (const u64x2*)(Wq + (size_t)(i+1)*DD);
            u64 acc[2][G];
            #pragma unroll
            for (int g = 0; g < G; g++) { acc[0][g] = 0ull; acc[1][g] = 0ull; }
            #pragma unroll
            for (int m = 0; m < 4; m++) {
                u64x2 wv0 = wrow0[lane + 32*m];
                u64x2 wv1 = wrow1[lane + 32*m];
                #pragma unroll
                for (int g = 0; g < G; g++) {
                    acc[0][g] = ffma2(wv0.x, xr[g][m].x, acc[0][g]);
                    acc[0][g] = ffma2(wv0.y, xr[g][m].y, acc[0][g]);
                    acc[1][g] = ffma2(wv1.x, xr[g][m].x, acc[1][g]);
                    acc[1][g] = ffma2(wv1.y, xr[g][m].y, acc[1][g]);
                }
            }
            // value idx = r*4+g: lane l -> g = l&3, r = (l>>2)&1
            float v = reduce8(hsum2(acc[0][0]), hsum2(acc[0][1]), hsum2(acc[0][2]), hsum2(acc[0][3]),
                              hsum2(acc[1][0]), hsum2(acc[1][1]), hsum2(acc[1][2]), hsum2(acc[1][3]),
                              lane);
            if (lane < 8) {
                const int ii = i + ((lane >> 2) & 1);
                qs[(lane & 3)*DD + ii] = v + __ldg(bq + ii);
            }
        }
    }
    __syncthreads();

    // ---- phase 2: qt[g][n][j] = sum_d Wk[n*64+d][j]·q[g][n*64+d] ; qb[g][n] = q·bk_n ----
    {
        for (int idx = tid; idx < NHH*128; idx += THREADS) {   // (n, j4)
            const int n  = idx >> 7;
            const int j4 = idx & 127;
            u64 acc[G][2];
            #pragma unroll
            for (int g = 0; g < G; g++) { acc[g][0] = 0ull; acc[g][1] = 0ull; }
            const u64x2* wk2 = (const u64x2*)Wk + (size_t)(n*64)*128 + j4;
            #pragma unroll 4
            for (int d = 0; d < 64; d++) {
                u64x2 wv = wk2[(size_t)d*128];
                #pragma unroll
                for (int g = 0; g < G; g++) {
                    float qv = qs[g*DD + n*64 + d];
                    u64 qp = pack2(qv, qv);
                    acc[g][0] = ffma2(wv.x, qp, acc[g][0]);
                    acc[g][1] = ffma2(wv.y, qp, acc[g][1]);
                }
            }
            #pragma unroll
            for (int g = 0; g < G; g++) {
                u64x2 t; t.x = acc[g][0]; t.y = acc[g][1];
                qtu2[g*1024 + idx] = t;
            }
        }
        if (tid < G*NHH) {
            const int gg = tid >> 3, n = tid & 7;
            float s = 0.f;
            for (int d = 0; d < 64; d++) s += qs[gg*DD + n*64 + d] * bk[n*64 + d];
            qb[tid] = s;
        }
    }
    __syncthreads();

    // ---- per-batch attention (two passes) ----
    for (int g = 0; g < G; g++) {
        const int b = b0 + g;
        const float4* xb4 = (const float4*)(x_seq + (size_t)b * SS * DD);  // 4096 float4/tile

        // hoist qt lane slices for this warp's 4 heads (pass-1), packed
        u64x2 qtr[4][4];
        #pragma unroll
        for (int h = 0; h < 4; h++)
            #pragma unroll
            for (int m = 0; m < 4; m++)
                qtr[h][m] = qtu2[g*1024 + (hq*4+h)*128 + lane + 32*m];

        // prime tile 0 into buf0
        {
            #pragma unroll
            for (int i = 0; i < 8; i++) cp16(&xs4[tid + 512*i], &xb4[tid + 512*i]);
            cp_commit();
        }

        // ---- pass 1: raw scores (bias added in softmax) ----
        for (int t = 0; t < NT; t++) {
            __syncthreads();   // everyone done with buf[(t+1)&1]'s old contents
            if (t + 1 < NT) {
                float4* dst = xs4 + ((t+1)&1)*4096;
                const float4* src = xb4 + (size_t)(t+1)*4096;
                #pragma unroll
                for (int i = 0; i < 8; i++) cp16(&dst[tid + 512*i], &src[tid + 512*i]);
                cp_commit();
                cp_wait<1>();
            } else {
                cp_wait<0>();
            }
            __syncthreads();   // tile t visible to all

            const float* buf = xs + (t&1)*BUF_F;
            const int base = sl1*4;
            const u64x2* xr0 = (const u64x2*)(buf + (base+0)*DD);
            const u64x2* xr1 = (const u64x2*)(buf + (base+1)*DD);
            const u64x2* xr2 = (const u64x2*)(buf + (base+2)*DD);
            const u64x2* xr3 = (const u64x2*)(buf + (base+3)*DD);

            u64 acc[4][4];   // [h][r]
            #pragma unroll
            for (int h = 0; h < 4; h++)
                #pragma unroll
                for (int r = 0; r < 4; r++) acc[h][r] = 0ull;

            #pragma unroll
            for (int m = 0; m < 4; m++) {
                u64x2 x0 = xr0[lane + 32*m];
                u64x2 x1 = xr1[lane + 32*m];
                u64x2 x2 = xr2[lane + 32*m];
                u64x2 x3 = xr3[lane + 32*m];
                #pragma unroll
                for (int h = 0; h < 4; h++) {
                    acc[h][0] = ffma2(x0.x, qtr[h][m].x, acc[h][0]);
                    acc[h][0] = ffma2(x0.y, qtr[h][m].y, acc[h][0]);
                    acc[h][1] = ffma2(x1.x, qtr[h][m].x, acc[h][1]);
                    acc[h][1] = ffma2(x1.y, qtr[h][m].y, acc[h][1]);
                    acc[h][2] = ffma2(x2.x, qtr[h][m].x, acc[h][2]);
                    acc[h][2] = ffma2(x2.y, qtr[h][m].y, acc[h][2]);
                    acc[h][3] = ffma2(x3.x, qtr[h][m].x, acc[h][3]);
                    acc[h][3] = ffma2(x3.y, qtr[h][m].y, acc[h][3]);
                }
            }
            // two interleaved reduce8s: value idx = r*4+h -> lane l: h = l&3, r = (l>>2)&1
            float vA = reduce8(hsum2(acc[0][0]), hsum2(acc[1][0]), hsum2(acc[2][0]), hsum2(acc[3][0]),
                               hsum2(acc[0][1]), hsum2(acc[1][1]), hsum2(acc[2][1]), hsum2(acc[3][1]),
                               lane);
            float vB = reduce8(hsum2(acc[0][2]), hsum2(acc[1][2]), hsum2(acc[2][2]), hsum2(acc[3][2]),
                               hsum2(acc[0][3]), hsum2(acc[1][3]), hsum2(acc[2][3]), hsum2(acc[3][3]),
                               lane);
            if (lane < 8) {
                const int h = lane & 3;
                const int r = (lane >> 2) & 1;
                float* scp = sc + g*1024 + (hq*4 + h)*SS + t*TS + base;
                scp[r]     = vA;
                scp[2 + r] = vB;
            }
        }
        __syncthreads();

        // ---- softmax (warps 0..7, warp w -> head w) ----
        if (w < NHH) {
            const int* mrow = mask + ((size_t)b*NHH + w)*SS;
            const float qbb = qb[g*NHH + w];
            float l[4];
            #pragma unroll
            for (int k = 0; k < 4; k++) {
                const int s = lane + 32*k;
                float raw = sc[g*1024 + w*SS + s] + qbb;
                l[k] = (mrow[s] != 0) ? floorf(raw * 0.125f) : -1e30f;
            }
            float mx = fmaxf(fmaxf(l[0],l[1]), fmaxf(l[2],l[3]));
            mx = warp_max(mx);
            float e[4]; float ssum = 0.f;
            #pragma unroll
            for (int k = 0; k < 4; k++) { e[k] = __expf(l[k] - mx); ssum += e[k]; }
            ssum = warp_sum(ssum);
            const float inv = 1.0f / ssum;
            #pragma unroll
            for (int k = 0; k < 4; k++)
                sc[g*1024 + w*SS + lane + 32*k] = e[k] * inv;
        }
        __syncthreads();

        // ---- pass 2 (reverse tiles; 3 and 2 still resident from pass 1) ----
        {
            const int h0 = hp*2;
            u64 ua0[8], ua1[8];
            #pragma unroll
            for (int m = 0; m < 8; m++) { ua0[m] = 0ull; ua1[m] = 0ull; }

            for (int t = NT-1; t >= 0; t--) {
                if (t <= NT-3) {              // prefetched tile: wait for it
                    if (t > 0) cp_wait<1>(); else cp_wait<0>();
                    __syncthreads();
                }
                const float* buf = xs + (t&1)*BUF_F;
                #pragma unroll 2
                for (int r = 0; r < 8; r++) {
                    const int srow = sl2*8 + r;
                    const float w0s = sc[g*1024 + (h0+0)*SS + t*TS + srow];
                    const float w1s = sc[g*1024 + (h0+1)*SS + t*TS + srow];
                    const u64 w0p = pack2(w0s, w0s);
                    const u64 w1p = pack2(w1s, w1s);
                    const u64x2* xr = (const u64x2*)(buf + srow*DD);
                    #pragma unroll
                    for (int m = 0; m < 4; m++) {
                        u64x2 xv = xr[lane + 32*m];
                        ua0[2*m+0] = ffma2(w0p, xv.x, ua0[2*m+0]);
                        ua0[2*m+1] = ffma2(w0p, xv.y, ua0[2*m+1]);
                        ua1[2*m+0] = ffma2(w1p, xv.x, ua1[2*m+0]);
                        ua1[2*m+1] = ffma2(w1p, xv.y, ua1[2*m+1]);
                    }
                }
                __syncthreads();    // done reading buf[t&1]
                if (t - 2 >= 0) {   // prefetch tile t-2 into the buffer just freed
                    float4* dst = xs4 + (t&1)*4096;
                    const float4* src = xb4 + (size_t)(t-2)*4096;
                    #pragma unroll
                    for (int i = 0; i < 8; i++) cp16(&dst[tid + 512*i], &src[tid + 512*i]);
                    cp_commit();
                }
            }

            // dump partials into xs scratch: [sl2][head][512]  (16K floats; xs holds 32K)
            u64x2* xs2 = (u64x2*)xs;
            #pragma unroll
            for (int m = 0; m < 4; m++) {
                u64x2 t0; t0.x = ua0[2*m+0]; t0.y = ua0[2*m+1];
                u64x2 t1; t1.x = ua1[2*m+0]; t1.y = ua1[2*m+1];
                xs2[(sl2*8 + h0+0)*128 + lane + 32*m] = t0;
                xs2[(sl2*8 + h0+1)*128 + lane + 32*m] = t1;
            }
            __syncthreads();
            // reduce across the 4 s-slices -> u in qtu[g]
            for (int idx = tid; idx < NHH*128; idx += THREADS) {
                float4 s0 = xs4[0*1024 + idx];
                float4 s1 = xs4[1*1024 + idx];
                float4 s2 = xs4[2*1024 + idx];
                float4 s3 = xs4[3*1024 + idx];
                float4 r;
                r.x = (s0.x + s1.x) + (s2.x + s3.x);
                r.y = (s0.y + s1.y) + (s2.y + s3.y);
                r.z = (s0.z + s1.z) + (s2.z + s3.z);
                r.w = (s0.w + s1.w) + (s2.w + s3.w);
                qtu4[g*1024 + idx] = r;
            }
            __syncthreads();   // scratch consumed before next batch's priming
        }
    } // batches

    // ---- phase z: out[b_g][i] = Wv[i,:]·u[g][head(i)] + bv[i]  (2 rows per iter) ----
    {
        const int zn = w >> 1;   // head for this warp's rows
        u64x2 ur[G][4];
        #pragma unroll
        for (int g = 0; g < G; g++)
            #pragma unroll
            for (int m = 0; m < 4; m++)
                ur[g][m] = qtu2[g*1024 + zn*128 + lane + 32*m];

        for (int rr = 0; rr < 32; rr += 2) {
            const int i = w*32 + rr;
            const u64x2* wrow0 = (const u64x2*)(Wv + (size_t)i*DD);
            const u64x2* wrow1 = (const u64x2*)(Wv + (size_t)(i+1)*DD);
            u64 acc[2][G];
            #pragma unroll
            for (int g = 0; g < G; g++) { acc[0][g] = 0ull; acc[1][g] = 0ull; }
            #pragma unroll
            for (int m = 0; m < 4; m++) {
                u64x2 wv0 = wrow0[lane + 32*m];
                u64x2 wv1 = wrow1[lane + 32*m];
                #pragma unroll
                for (int g = 0; g < G; g++) {
                    acc[0][g] = ffma2(wv0.x, ur[g][m].x, acc[0][g]);
                    acc[0][g] = ffma2(wv0.y, ur[g][m].y, acc[0][g]);
                    acc[1][g] = ffma2(wv1.x, ur[g][m].x, acc[1][g]);
                    acc[1][g] = ffma2(wv1.y, ur[g][m].y, acc[1][g]);
                }
            }
            float v = reduce8(hsum2(acc[0][0]), hsum2(acc[0][1]), hsum2(acc[0][2]), hsum2(acc[0][3]),
                              hsum2(acc[1][0]), hsum2(acc[1][1]), hsum2(acc[1][2]), hsum2(acc[1][3]),
                              lane);
            if (lane < 8) {
                const int ii = i + ((lane >> 2) & 1);
                out[(size_t)(b0 + (lane & 3))*DD + ii] = v + __ldg(bv + ii);
            }
        }
    }
}

extern "C" void kernel_launch(void* const* d_in, const int* in_sizes, int n_in,
                              void* d_out, int out_size)
{
    const float* x_non = (const float*)d_in[0];
    const float* x_seq = (const float*)d_in[1];
    const int*   mask  = (const int*)  d_in[2];
    const float* Wq    = (const float*)d_in[3];
    const float* bq    = (const float*)d_in[4];
    const float* Wk    = (const float*)d_in[5];
    const float* bk    = (const float*)d_in[6];
    const float* Wv    = (const float*)d_in[7];
    const float* bv    = (const float*)d_in[8];
    float* out = (float*)d_out;

    const int smem_bytes = SMEM_F * (int)sizeof(float);   // ~216 KB
    cudaFuncSetAttribute(mha_kernel, cudaFuncAttributeMaxDynamicSharedMemorySize, smem_bytes);
    mha_kernel<<<1024/G, THREADS, smem_bytes>>>(x_non, x_seq, mask,
                                                Wq, bq, Wk, bk, Wv, bv, out);
}

// round 14
// speedup vs baseline: 1.5847x; 1.0328x over previous
#include <cuda_runtime.h>
#include <math.h>

#define G   4          // batches per CTA
#define TS  32         // x_seq tile rows per buffer
#define NT  4          // tiles per batch (128/TS)
#define NHH 8
#define DD  512
#define SS  128
#define THREADS 512    // 16 warps

// SMEM float counts
#define BUF_F   (TS*DD)              // 16384 per buffer
#define XS_F    (2*BUF_F)            // 32768 (double buffer; also pass-2 partial scratch [4][8][512])
#define QTU_F   (G*NHH*DD)           // 16384  (qt, later reused as u)
#define QS_F    (G*DD)               // 2048
#define SC_F    (G*NHH*SS)           // 4096   (scores -> attn; also x_non staging)
#define QB_F    (G*NHH)              // 32
#define SMEM_F  (XS_F + QTU_F + QS_F + SC_F + QB_F)   // ~216 KB

typedef unsigned long long u64;
typedef ulonglong2 u64x2;

// packed f32x2 fused multiply-add: d = a*b + c elementwise on (lo,hi) pairs
__device__ __forceinline__ u64 ffma2(u64 a, u64 b, u64 c) {
    u64 d;
    asm("fma.rn.f32x2 %0, %1, %2, %3;" : "=l"(d) : "l"(a), "l"(b), "l"(c));
    return d;
}
__device__ __forceinline__ u64 pack2(float lo, float hi) {
    u64 d; asm("mov.b64 %0, {%1, %2};" : "=l"(d) : "f"(lo), "f"(hi)); return d;
}
__device__ __forceinline__ float hsum2(u64 a) {
    float lo, hi;
    asm("mov.b64 {%0, %1}, %2;" : "=f"(lo), "=f"(hi) : "l"(a));
    return lo + hi;
}

__device__ __forceinline__ float warp_sum(float v) {
    v += __shfl_xor_sync(0xffffffffu, v, 16);
    v += __shfl_xor_sync(0xffffffffu, v, 8);
    v += __shfl_xor_sync(0xffffffffu, v, 4);
    v += __shfl_xor_sync(0xffffffffu, v, 2);
    v += __shfl_xor_sync(0xffffffffu, v, 1);
    return v;
}
__device__ __forceinline__ float warp_max(float v) {
    v = fmaxf(v, __shfl_xor_sync(0xffffffffu, v, 16));
    v = fmaxf(v, __shfl_xor_sync(0xffffffffu, v, 8));
    v = fmaxf(v, __shfl_xor_sync(0xffffffffu, v, 4));
    v = fmaxf(v, __shfl_xor_sync(0xffffffffu, v, 2));
    v = fmaxf(v, __shfl_xor_sync(0xffffffffu, v, 1));
    return v;
}

// 8 complete warp sums in 26 shuffles, single depth-5 chain.
// Every lane returns total of value (lane&7); lanes 0..7 together hold all 8.
__device__ __forceinline__ float reduce8(float a0, float a1, float a2, float a3,
                                         float a4, float a5, float a6, float a7,
                                         int lane) {
    a0 += __shfl_xor_sync(0xffffffffu, a0, 4);
    a1 += __shfl_xor_sync(0xffffffffu, a1, 4);
    a2 += __shfl_xor_sync(0xffffffffu, a2, 4);
    a3 += __shfl_xor_sync(0xffffffffu, a3, 4);
    a4 += __shfl_xor_sync(0xffffffffu, a4, 4);
    a5 += __shfl_xor_sync(0xffffffffu, a5, 4);
    a6 += __shfl_xor_sync(0xffffffffu, a6, 4);
    a7 += __shfl_xor_sync(0xffffffffu, a7, 4);
    a0 += __shfl_xor_sync(0xffffffffu, a0, 2);
    a1 += __shfl_xor_sync(0xffffffffu, a1, 2);
    a2 += __shfl_xor_sync(0xffffffffu, a2, 2);
    a3 += __shfl_xor_sync(0xffffffffu, a3, 2);
    a4 += __shfl_xor_sync(0xffffffffu, a4, 2);
    a5 += __shfl_xor_sync(0xffffffffu, a5, 2);
    a6 += __shfl_xor_sync(0xffffffffu, a6, 2);
    a7 += __shfl_xor_sync(0xffffffffu, a7, 2);
    a0 += __shfl_xor_sync(0xffffffffu, a0, 1);
    a1 += __shfl_xor_sync(0xffffffffu, a1, 1);
    a2 += __shfl_xor_sync(0xffffffffu, a2, 1);
    a3 += __shfl_xor_sync(0xffffffffu, a3, 1);
    a4 += __shfl_xor_sync(0xffffffffu, a4, 1);
    a5 += __shfl_xor_sync(0xffffffffu, a5, 1);
    a6 += __shfl_xor_sync(0xffffffffu, a6, 1);
    a7 += __shfl_xor_sync(0xffffffffu, a7, 1);
    // lane l now holds the partial of its aligned-8 group (l>>3) for all 8 values
    float v = (lane & 4) ? ((lane & 2) ? ((lane & 1) ? a7 : a6) : ((lane & 1) ? a5 : a4))
                         : ((lane & 2) ? ((lane & 1) ? a3 : a2) : ((lane & 1) ? a1 : a0));
    v += __shfl_xor_sync(0xffffffffu, v, 8);
    v += __shfl_xor_sync(0xffffffffu, v, 16);
    return v;
}

__device__ __forceinline__ void cp16(float4* dst_smem, const float4* src) {
    unsigned int d = (unsigned int)__cvta_generic_to_shared(dst_smem);
    asm volatile("cp.async.cg.shared.global [%0], [%1], 16;\n" :: "r"(d), "l"(src));
}
__device__ __forceinline__ void cp_commit() {
    asm volatile("cp.async.commit_group;\n" ::: "memory");
}
template <int N>
__device__ __forceinline__ void cp_wait() {
    asm volatile("cp.async.wait_group %0;\n" :: "n"(N) : "memory");
}

__global__ __launch_bounds__(THREADS, 1)
void mha_kernel(const float* __restrict__ x_non,
                const float* __restrict__ x_seq,
                const int*   __restrict__ mask,
                const float* __restrict__ Wq, const float* __restrict__ bq,
                const float* __restrict__ Wk, const float* __restrict__ bk,
                const float* __restrict__ Wv, const float* __restrict__ bv,
                float* __restrict__ out)
{
    extern __shared__ float smem[];
    float* xs  = smem;                 // 2 x [TS][512]; later [4][8][512] partial-u scratch
    float* qtu = xs + XS_F;            // [G][8][512]  qt then u
    float* qs  = qtu + QTU_F;          // [G][512]
    float* sc  = qs + QS_F;            // [G][8][128]  scores/attn (and x_non staging)
    float* qb  = sc + SC_F;            // [G][8]

    float4* xs4  = (float4*)xs;
    float4* qtu4 = (float4*)qtu;
    u64x2*  qtu2 = (u64x2*)qtu;

    const int tid  = threadIdx.x;
    const int lane = tid & 31;
    const int w    = tid >> 5;         // 0..15
    const int b0   = blockIdx.x * G;

    // pass-1 mapping: head quad + 4-row slice
    const int hq  = w >> 3;            // 0..1 -> heads hq*4 .. hq*4+3
    const int sl1 = w & 7;             // rows [sl1*4, sl1*4+4) of 32-row tile
    // pass-2 mapping: head pair + 8-row slice
    const int hp  = w >> 2;            // 0..3 -> heads hp*2, hp*2+1
    const int sl2 = w & 3;             // rows [sl2*8, sl2*8+8) of tile

    // ---- stage x_non[b0..b0+G) into sc region ----
    for (int i = tid; i < G*DD; i += THREADS)
        sc[i] = x_non[(size_t)b0*DD + i];
    __syncthreads();

    // ---- phase 1: q[g][i] = Wq[i,:]·xn[g] + bq[i]  (warp w -> rows [w*32, w*32+32), 4 at a time) ----
    {
        const u64x2* xn2 = (const u64x2*)sc;
        u64x2 xr[G][4];
        #pragma unroll
        for (int g = 0; g < G; g++)
            #pragma unroll
            for (int m = 0; m < 4; m++)
                xr[g][m] = xn2[g*128 + lane + 32*m];

        for (int rr = 0; rr < 32; rr += 4) {
            const int i = w*32 + rr;
            u64 acc[4][G];
            #pragma unroll
            for (int r = 0; r < 4; r++)
                #pragma unroll
                for (int g = 0; g < G; g++) acc[r][g] = 0ull;
            #pragma unroll
            for (int m = 0; m < 4; m++) {
                #pragma unroll
                for (int r = 0; r < 4; r++) {
                    u64x2 wv = ((const u64x2*)(Wq + (size_t)(i+r)*DD))[lane + 32*m];
                    #pragma unroll
                    for (int g = 0; g < G; g++) {
                        acc[r][g] = ffma2(wv.x, xr[g][m].x, acc[r][g]);
                        acc[r][g] = ffma2(wv.y, xr[g][m].y, acc[r][g]);
                    }
                }
            }
            // two independent reduce8s: value idx = r*4+g (r within pair), lane l -> g=l&3, r=(l>>2)&1
            float vA = reduce8(hsum2(acc[0][0]), hsum2(acc[0][1]), hsum2(acc[0][2]), hsum2(acc[0][3]),
                               hsum2(acc[1][0]), hsum2(acc[1][1]), hsum2(acc[1][2]), hsum2(acc[1][3]),
                               lane);
            float vB = reduce8(hsum2(acc[2][0]), hsum2(acc[2][1]), hsum2(acc[2][2]), hsum2(acc[2][3]),
                               hsum2(acc[3][0]), hsum2(acc[3][1]), hsum2(acc[3][2]), hsum2(acc[3][3]),
                               lane);
            if (lane < 8) {
                const int g  = lane & 3;
                const int r  = (lane >> 2) & 1;
                const int iA = i + r;
                const int iB = i + 2 + r;
                qs[g*DD + iA] = vA + __ldg(bq + iA);
                qs[g*DD + iB] = vB + __ldg(bq + iB);
            }
        }
    }
    __syncthreads();

    // ---- phase 2: qt[g][n][j] = sum_d Wk[n*64+d][j]·q[g][n*64+d] ; qb[g][n] = q·bk_n ----
    {
        for (int idx = tid; idx < NHH*128; idx += THREADS) {   // (n, j4)
            const int n  = idx >> 7;
            const int j4 = idx & 127;
            u64 acc[G][2];
            #pragma unroll
            for (int g = 0; g < G; g++) { acc[g][0] = 0ull; acc[g][1] = 0ull; }
            const u64x2* wk2 = (const u64x2*)Wk + (size_t)(n*64)*128 + j4;
            #pragma unroll 4
            for (int d = 0; d < 64; d++) {
                u64x2 wv = wk2[(size_t)d*128];
                #pragma unroll
                for (int g = 0; g < G; g++) {
                    float qv = qs[g*DD + n*64 + d];
                    u64 qp = pack2(qv, qv);
                    acc[g][0] = ffma2(wv.x, qp, acc[g][0]);
                    acc[g][1] = ffma2(wv.y, qp, acc[g][1]);
                }
            }
            #pragma unroll
            for (int g = 0; g < G; g++) {
                u64x2 t; t.x = acc[g][0]; t.y = acc[g][1];
                qtu2[g*1024 + idx] = t;
            }
        }
        if (tid < G*NHH) {
            const int gg = tid >> 3, n = tid & 7;
            float s = 0.f;
            for (int d = 0; d < 64; d++) s += qs[gg*DD + n*64 + d] * bk[n*64 + d];
            qb[tid] = s;
        }
    }
    __syncthreads();

    // ---- per-batch attention (two passes) ----
    for (int g = 0; g < G; g++) {
        const int b = b0 + g;
        const float4* xb4 = (const float4*)(x_seq + (size_t)b * SS * DD);  // 4096 float4/tile

        // hoist qt lane slices for this warp's 4 heads (pass-1), packed
        u64x2 qtr[4][4];
        #pragma unroll
        for (int h = 0; h < 4; h++)
            #pragma unroll
            for (int m = 0; m < 4; m++)
                qtr[h][m] = qtu2[g*1024 + (hq*4+h)*128 + lane + 32*m];

        // prime tile 0 into buf0
        {
            #pragma unroll
            for (int i = 0; i < 8; i++) cp16(&xs4[tid + 512*i], &xb4[tid + 512*i]);
            cp_commit();
        }

        // ---- pass 1: raw scores (bias added in softmax) ----
        for (int t = 0; t < NT; t++) {
            __syncthreads();   // everyone done with buf[(t+1)&1]'s old contents
            if (t + 1 < NT) {
                float4* dst = xs4 + ((t+1)&1)*4096;
                const float4* src = xb4 + (size_t)(t+1)*4096;
                #pragma unroll
                for (int i = 0; i < 8; i++) cp16(&dst[tid + 512*i], &src[tid + 512*i]);
                cp_commit();
                cp_wait<1>();
            } else {
                cp_wait<0>();
            }
            __syncthreads();   // tile t visible to all

            const float* buf = xs + (t&1)*BUF_F;
            const int base = sl1*4;
            const u64x2* xr0 = (const u64x2*)(buf + (base+0)*DD);
            const u64x2* xr1 = (const u64x2*)(buf + (base+1)*DD);
            const u64x2* xr2 = (const u64x2*)(buf + (base+2)*DD);
            const u64x2* xr3 = (const u64x2*)(buf + (base+3)*DD);

            u64 acc[4][4];   // [h][r]
            #pragma unroll
            for (int h = 0; h < 4; h++)
                #pragma unroll
                for (int r = 0; r < 4; r++) acc[h][r] = 0ull;

            #pragma unroll
            for (int m = 0; m < 4; m++) {
                u64x2 x0 = xr0[lane + 32*m];
                u64x2 x1 = xr1[lane + 32*m];
                u64x2 x2 = xr2[lane + 32*m];
                u64x2 x3 = xr3[lane + 32*m];
                #pragma unroll
                for (int h = 0; h < 4; h++) {
                    acc[h][0] = ffma2(x0.x, qtr[h][m].x, acc[h][0]);
                    acc[h][0] = ffma2(x0.y, qtr[h][m].y, acc[h][0]);
                    acc[h][1] = ffma2(x1.x, qtr[h][m].x, acc[h][1]);
                    acc[h][1] = ffma2(x1.y, qtr[h][m].y, acc[h][1]);
                    acc[h][2] = ffma2(x2.x, qtr[h][m].x, acc[h][2]);
                    acc[h][2] = ffma2(x2.y, qtr[h][m].y, acc[h][2]);
                    acc[h][3] = ffma2(x3.x, qtr[h][m].x, acc[h][3]);
                    acc[h][3] = ffma2(x3.y, qtr[h][m].y, acc[h][3]);
                }
            }
            // two interleaved reduce8s: value idx = r*4+h -> lane l: h = l&3, r = (l>>2)&1
            float vA = reduce8(hsum2(acc[0][0]), hsum2(acc[1][0]), hsum2(acc[2][0]), hsum2(acc[3][0]),
                               hsum2(acc[0][1]), hsum2(acc[1][1]), hsum2(acc[2][1]), hsum2(acc[3][1]),
                               lane);
            float vB = reduce8(hsum2(acc[0][2]), hsum2(acc[1][2]), hsum2(acc[2][2]), hsum2(acc[3][2]),
                               hsum2(acc[0][3]), hsum2(acc[1][3]), hsum2(acc[2][3]), hsum2(acc[3][3]),
                               lane);
            if (lane < 8) {
                const int h = lane & 3;
                const int r = (lane >> 2) & 1;
                float* scp = sc + g*1024 + (hq*4 + h)*SS + t*TS + base;
                scp[r]     = vA;
                scp[2 + r] = vB;
            }
        }
        __syncthreads();

        // ---- softmax (warps 0..7, warp w -> head w) ----
        if (w < NHH) {
            const int* mrow = mask + ((size_t)b*NHH + w)*SS;
            const float qbb = qb[g*NHH + w];
            float l[4];
            #pragma unroll
            for (int k = 0; k < 4; k++) {
                const int s = lane + 32*k;
                float raw = sc[g*1024 + w*SS + s] + qbb;
                l[k] = (mrow[s] != 0) ? floorf(raw * 0.125f) : -1e30f;
            }
            float mx = fmaxf(fmaxf(l[0],l[1]), fmaxf(l[2],l[3]));
            mx = warp_max(mx);
            float e[4]; float ssum = 0.f;
            #pragma unroll
            for (int k = 0; k < 4; k++) { e[k] = __expf(l[k] - mx); ssum += e[k]; }
            ssum = warp_sum(ssum);
            const float inv = 1.0f / ssum;
            #pragma unroll
            for (int k = 0; k < 4; k++)
                sc[g*1024 + w*SS + lane + 32*k] = e[k] * inv;
        }
        __syncthreads();

        // ---- pass 2 (reverse tiles; 3 and 2 still resident from pass 1) ----
        {
            const int h0 = hp*2;
            u64 ua0[8], ua1[8];
            #pragma unroll
            for (int m = 0; m < 8; m++) { ua0[m] = 0ull; ua1[m] = 0ull; }

            for (int t = NT-1; t >= 0; t--) {
                if (t <= NT-3) {              // prefetched tile: wait for it
                    if (t > 0) cp_wait<1>(); else cp_wait<0>();
                    __syncthreads();
                }
                const float* buf = xs + (t&1)*BUF_F;
                #pragma unroll
                for (int r = 0; r < 8; r++) {
                    const int srow = sl2*8 + r;
                    const float w0s = sc[g*1024 + (h0+0)*SS + t*TS + srow];
                    const float w1s = sc[g*1024 + (h0+1)*SS + t*TS + srow];
                    const u64 w0p = pack2(w0s, w0s);
                    const u64 w1p = pack2(w1s, w1s);
                    const u64x2* xr = (const u64x2*)(buf + srow*DD);
                    #pragma unroll
                    for (int m = 0; m < 4; m++) {
                        u64x2 xv = xr[lane + 32*m];
                        ua0[2*m+0] = ffma2(w0p, xv.x, ua0[2*m+0]);
                        ua0[2*m+1] = ffma2(w0p, xv.y, ua0[2*m+1]);
                        ua1[2*m+0] = ffma2(w1p, xv.x, ua1[2*m+0]);
                        ua1[2*m+1] = ffma2(w1p, xv.y, ua1[2*m+1]);
                    }
                }
                __syncthreads();    // done reading buf[t&1]
                if (t - 2 >= 0) {   // prefetch tile t-2 into the buffer just freed
                    float4* dst = xs4 + (t&1)*4096;
                    const float4* src = xb4 + (size_t)(t-2)*4096;
                    #pragma unroll
                    for (int i = 0; i < 8; i++) cp16(&dst[tid + 512*i], &src[tid + 512*i]);
                    cp_commit();
                }
            }

            // dump partials into xs scratch: [sl2][head][512]  (16K floats; xs holds 32K)
            u64x2* xs2 = (u64x2*)xs;
            #pragma unroll
            for (int m = 0; m < 4; m++) {
                u64x2 t0; t0.x = ua0[2*m+0]; t0.y = ua0[2*m+1];
                u64x2 t1; t1.x = ua1[2*m+0]; t1.y = ua1[2*m+1];
                xs2[(sl2*8 + h0+0)*128 + lane + 32*m] = t0;
                xs2[(sl2*8 + h0+1)*128 + lane + 32*m] = t1;
            }
            __syncthreads();
            // reduce across the 4 s-slices -> u in qtu[g]
            for (int idx = tid; idx < NHH*128; idx += THREADS) {
                float4 s0 = xs4[0*1024 + idx];
                float4 s1 = xs4[1*1024 + idx];
                float4 s2 = xs4[2*1024 + idx];
                float4 s3 = xs4[3*1024 + idx];
                float4 r;
                r.x = (s0.x + s1.x) + (s2.x + s3.x);
                r.y = (s0.y + s1.y) + (s2.y + s3.y);
                r.z = (s0.z + s1.z) + (s2.z + s3.z);
                r.w = (s0.w + s1.w) + (s2.w + s3.w);
                qtu4[g*1024 + idx] = r;
            }
            __syncthreads();   // scratch consumed before next batch's priming
        }
    } // batches

    // ---- phase z: out[b_g][i] = Wv[i,:]·u[g][head(i)] + bv[i]  (4 rows per iter) ----
    {
        const int zn = w >> 1;   // head for this warp's rows
        u64x2 ur[G][4];
        #pragma unroll
        for (int g = 0; g < G; g++)
            #pragma unroll
            for (int m = 0; m < 4; m++)
                ur[g][m] = qtu2[g*1024 + zn*128 + lane + 32*m];

        for (int rr = 0; rr < 32; rr += 4) {
            const int i = w*32 + rr;
            u64 acc[4][G];
            #pragma unroll
            for (int r = 0; r < 4; r++)
                #pragma unroll
                for (int g = 0; g < G; g++) acc[r][g] = 0ull;
            #pragma unroll
            for (int m = 0; m < 4; m++) {
                #pragma unroll
                for (int r = 0; r < 4; r++) {
                    u64x2 wv = ((const u64x2*)(Wv + (size_t)(i+r)*DD))[lane + 32*m];
                    #pragma unroll
                    for (int g = 0; g < G; g++) {
                        acc[r][g] = ffma2(wv.x, ur[g][m].x, acc[r][g]);
                        acc[r][g] = ffma2(wv.y, ur[g][m].y, acc[r][g]);
                    }
                }
            }
            float vA = reduce8(hsum2(acc[0][0]), hsum2(acc[0][1]), hsum2(acc[0][2]), hsum2(acc[0][3]),
                               hsum2(acc[1][0]), hsum2(acc[1][1]), hsum2(acc[1][2]), hsum2(acc[1][3]),
                               lane);
            float vB = reduce8(hsum2(acc[2][0]), hsum2(acc[2][1]), hsum2(acc[2][2]), hsum2(acc[2][3]),
                               hsum2(acc[3][0]), hsum2(acc[3][1]), hsum2(acc[3][2]), hsum2(acc[3][3]),
                               lane);
            if (lane < 8) {
                const int g  = lane & 3;
                const int r  = (lane >> 2) & 1;
                const int iA = i + r;
                const int iB = i + 2 + r;
                out[(size_t)(b0 + g)*DD + iA] = vA + __ldg(bv + iA);
                out[(size_t)(b0 + g)*DD + iB] = vB + __ldg(bv + iB);
            }
        }
    }
}

extern "C" void kernel_launch(void* const* d_in, const int* in_sizes, int n_in,
                              void* d_out, int out_size)
{
    const float* x_non = (const float*)d_in[0];
    const float* x_seq = (const float*)d_in[1];
    const int*   mask  = (const int*)  d_in[2];
    const float* Wq    = (const float*)d_in[3];
    const float* bq    = (const float*)d_in[4];
    const float* Wk    = (const float*)d_in[5];
    const float* bk    = (const float*)d_in[6];
    const float* Wv    = (const float*)d_in[7];
    const float* bv    = (const float*)d_in[8];
    float* out = (float*)d_out;

    const int smem_bytes = SMEM_F * (int)sizeof(float);   // ~216 KB
    cudaFuncSetAttribute(mha_kernel, cudaFuncAttributeMaxDynamicSharedMemorySize, smem_bytes);
    mha_kernel<<<1024/G, THREADS, smem_bytes>>>(x_non, x_seq, mask,
                                                Wq, bq, Wk, bk, Wv, bv, out);
}

// round 16
// speedup vs baseline: 1.6430x; 1.0368x over previous
#include <cuda_runtime.h>
#include <math.h>

#define G   4          // batches per CTA
#define TS  32         // x_seq tile rows per buffer
#define NT  4          // tiles per batch (128/TS)
#define NHH 8
#define DD  512
#define SS  128
#define THREADS 512    // 16 warps

// SMEM float counts
#define BUF_F   (TS*DD)              // 16384 per buffer
#define XS_F    (2*BUF_F)            // 32768 (double buffer; also pass-2 partial scratch [4][8][512])
#define QTU_F   (G*NHH*DD)           // 16384  (qt, later reused as u)
#define QS_F    (G*DD)               // 2048
#define SC_F    (G*NHH*SS)           // 4096   (raw scores; also x_non staging)
#define QB_F    (G*NHH)              // 32
#define SC2_F   (SS*NHH*2)           // 2048 floats = 1024 u64: packed attn (w,w) [s][h]
#define SMEM_F  (XS_F + QTU_F + QS_F + SC_F + QB_F + SC2_F)   // ~229.5 KB

typedef unsigned long long u64;
typedef ulonglong2 u64x2;

// packed f32x2 fused multiply-add: d = a*b + c elementwise on (lo,hi) pairs
__device__ __forceinline__ u64 ffma2(u64 a, u64 b, u64 c) {
    u64 d;
    asm("fma.rn.f32x2 %0, %1, %2, %3;" : "=l"(d) : "l"(a), "l"(b), "l"(c));
    return d;
}
__device__ __forceinline__ u64 pack2(float lo, float hi) {
    u64 d; asm("mov.b64 %0, {%1, %2};" : "=l"(d) : "f"(lo), "f"(hi)); return d;
}
__device__ __forceinline__ float hsum2(u64 a) {
    float lo, hi;
    asm("mov.b64 {%0, %1}, %2;" : "=f"(lo), "=f"(hi) : "l"(a));
    return lo + hi;
}

__device__ __forceinline__ float warp_sum(float v) {
    v += __shfl_xor_sync(0xffffffffu, v, 16);
    v += __shfl_xor_sync(0xffffffffu, v, 8);
    v += __shfl_xor_sync(0xffffffffu, v, 4);
    v += __shfl_xor_sync(0xffffffffu, v, 2);
    v += __shfl_xor_sync(0xffffffffu, v, 1);
    return v;
}
__device__ __forceinline__ float warp_max(float v) {
    v = fmaxf(v, __shfl_xor_sync(0xffffffffu, v, 16));
    v = fmaxf(v, __shfl_xor_sync(0xffffffffu, v, 8));
    v = fmaxf(v, __shfl_xor_sync(0xffffffffu, v, 4));
    v = fmaxf(v, __shfl_xor_sync(0xffffffffu, v, 2));
    v = fmaxf(v, __shfl_xor_sync(0xffffffffu, v, 1));
    return v;
}

// 8 complete warp sums in 26 shuffles, single depth-5 chain.
// Every lane returns total of value (lane&7); lanes 0..7 together hold all 8.
__device__ __forceinline__ float reduce8(float a0, float a1, float a2, float a3,
                                         float a4, float a5, float a6, float a7,
                                         int lane) {
    a0 += __shfl_xor_sync(0xffffffffu, a0, 4);
    a1 += __shfl_xor_sync(0xffffffffu, a1, 4);
    a2 += __shfl_xor_sync(0xffffffffu, a2, 4);
    a3 += __shfl_xor_sync(0xffffffffu, a3, 4);
    a4 += __shfl_xor_sync(0xffffffffu, a4, 4);
    a5 += __shfl_xor_sync(0xffffffffu, a5, 4);
    a6 += __shfl_xor_sync(0xffffffffu, a6, 4);
    a7 += __shfl_xor_sync(0xffffffffu, a7, 4);
    a0 += __shfl_xor_sync(0xffffffffu, a0, 2);
    a1 += __shfl_xor_sync(0xffffffffu, a1, 2);
    a2 += __shfl_xor_sync(0xffffffffu, a2, 2);
    a3 += __shfl_xor_sync(0xffffffffu, a3, 2);
    a4 += __shfl_xor_sync(0xffffffffu, a4, 2);
    a5 += __shfl_xor_sync(0xffffffffu, a5, 2);
    a6 += __shfl_xor_sync(0xffffffffu, a6, 2);
    a7 += __shfl_xor_sync(0xffffffffu, a7, 2);
    a0 += __shfl_xor_sync(0xffffffffu, a0, 1);
    a1 += __shfl_xor_sync(0xffffffffu, a1, 1);
    a2 += __shfl_xor_sync(0xffffffffu, a2, 1);
    a3 += __shfl_xor_sync(0xffffffffu, a3, 1);
    a4 += __shfl_xor_sync(0xffffffffu, a4, 1);
    a5 += __shfl_xor_sync(0xffffffffu, a5, 1);
    a6 += __shfl_xor_sync(0xffffffffu, a6, 1);
    a7 += __shfl_xor_sync(0xffffffffu, a7, 1);
    float v = (lane & 4) ? ((lane & 2) ? ((lane & 1) ? a7 : a6) : ((lane & 1) ? a5 : a4))
                         : ((lane & 2) ? ((lane & 1) ? a3 : a2) : ((lane & 1) ? a1 : a0));
    v += __shfl_xor_sync(0xffffffffu, v, 8);
    v += __shfl_xor_sync(0xffffffffu, v, 16);
    return v;
}

__device__ __forceinline__ void cp16(float4* dst_smem, const float4* src) {
    unsigned int d = (unsigned int)__cvta_generic_to_shared(dst_smem);
    asm volatile("cp.async.cg.shared.global [%0], [%1], 16;\n" :: "r"(d), "l"(src));
}
__device__ __forceinline__ void cp_commit() {
    asm volatile("cp.async.commit_group;\n" ::: "memory");
}
template <int N>
__device__ __forceinline__ void cp_wait() {
    asm volatile("cp.async.wait_group %0;\n" :: "n"(N) : "memory");
}

__global__ __launch_bounds__(THREADS, 1)
void mha_kernel(const float* __restrict__ x_non,
                const float* __restrict__ x_seq,
                const int*   __restrict__ mask,
                const float* __restrict__ Wq, const float* __restrict__ bq,
                const float* __restrict__ Wk, const float* __restrict__ bk,
                const float* __restrict__ Wv, const float* __restrict__ bv,
                float* __restrict__ out)
{
    extern __shared__ float smem[];
    float* xs   = smem;                 // 2 x [TS][512]; later [4][8][512] partial-u scratch
    float* qtu  = xs + XS_F;            // [G][8][512]  qt then u
    float* qs   = qtu + QTU_F;          // [G][512]
    float* sc   = qs + QS_F;            // [G][8][128]  raw scores (and x_non staging)
    float* qb   = sc + SC_F;            // [G][8]
    u64*   sc2  = (u64*)(qb + QB_F);    // [128 s][8 h] packed (w,w) attn weights, current batch

    float4* xs4  = (float4*)xs;
    float4* qtu4 = (float4*)qtu;
    u64x2*  qtu2 = (u64x2*)qtu;

    const int tid  = threadIdx.x;
    const int lane = tid & 31;
    const int w    = tid >> 5;         // 0..15
    const int b0   = blockIdx.x * G;

    // pass-1 mapping: head quad + 4-row slice
    const int hq  = w >> 3;            // 0..1 -> heads hq*4 .. hq*4+3
    const int sl1 = w & 7;             // rows [sl1*4, sl1*4+4) of 32-row tile
    // pass-2 mapping: column slice x row slice (tile read exactly once CTA-wide)
    const int cs  = w & 3;             // cols [cs*128, cs*128+128)
    const int rs  = w >> 2;            // rows [rs*8, rs*8+8)

    // ---- stage x_non[b0..b0+G) into sc region ----
    for (int i = tid; i < G*DD; i += THREADS)
        sc[i] = x_non[(size_t)b0*DD + i];
    __syncthreads();

    // ---- phase 1: q[g][i] = Wq[i,:]·xn[g] + bq[i]  (warp w -> rows [w*32, w*32+32), 4 at a time) ----
    {
        const u64x2* xn2 = (const u64x2*)sc;
        u64x2 xr[G][4];
        #pragma unroll
        for (int g = 0; g < G; g++)
            #pragma unroll
            for (int m = 0; m < 4; m++)
                xr[g][m] = xn2[g*128 + lane + 32*m];

        for (int rr = 0; rr < 32; rr += 4) {
            const int i = w*32 + rr;
            u64 acc[4][G];
            #pragma unroll
            for (int r = 0; r < 4; r++)
                #pragma unroll
                for (int g = 0; g < G; g++) acc[r][g] = 0ull;
            #pragma unroll
            for (int m = 0; m < 4; m++) {
                #pragma unroll
                for (int r = 0; r < 4; r++) {
                    u64x2 wv = ((const u64x2*)(Wq + (size_t)(i+r)*DD))[lane + 32*m];
                    #pragma unroll
                    for (int g = 0; g < G; g++) {
                        acc[r][g] = ffma2(wv.x, xr[g][m].x, acc[r][g]);
                        acc[r][g] = ffma2(wv.y, xr[g][m].y, acc[r][g]);
                    }
                }
            }
            float vA = reduce8(hsum2(acc[0][0]), hsum2(acc[0][1]), hsum2(acc[0][2]), hsum2(acc[0][3]),
                               hsum2(acc[1][0]), hsum2(acc[1][1]), hsum2(acc[1][2]), hsum2(acc[1][3]),
                               lane);
            float vB = reduce8(hsum2(acc[2][0]), hsum2(acc[2][1]), hsum2(acc[2][2]), hsum2(acc[2][3]),
                               hsum2(acc[3][0]), hsum2(acc[3][1]), hsum2(acc[3][2]), hsum2(acc[3][3]),
                               lane);
            if (lane < 8) {
                const int g  = lane & 3;
                const int r  = (lane >> 2) & 1;
                const int iA = i + r;
                const int iB = i + 2 + r;
                qs[g*DD + iA] = vA + __ldg(bq + iA);
                qs[g*DD + iB] = vB + __ldg(bq + iB);
            }
        }
    }
    __syncthreads();

    // ---- phase 2: qt[g][n][j] = sum_d Wk[n*64+d][j]·q[g][n*64+d] ; qb[g][n] = q·bk_n ----
    {
        for (int idx = tid; idx < NHH*128; idx += THREADS) {   // (n, j4)
            const int n  = idx >> 7;
            const int j4 = idx & 127;
            u64 acc[G][2];
            #pragma unroll
            for (int g = 0; g < G; g++) { acc[g][0] = 0ull; acc[g][1] = 0ull; }
            const u64x2* wk2 = (const u64x2*)Wk + (size_t)(n*64)*128 + j4;
            #pragma unroll 4
            for (int d = 0; d < 64; d++) {
                u64x2 wv = wk2[(size_t)d*128];
                #pragma unroll
                for (int g = 0; g < G; g++) {
                    float qv = qs[g*DD + n*64 + d];
                    u64 qp = pack2(qv, qv);
                    acc[g][0] = ffma2(wv.x, qp, acc[g][0]);
                    acc[g][1] = ffma2(wv.y, qp, acc[g][1]);
                }
            }
            #pragma unroll
            for (int g = 0; g < G; g++) {
                u64x2 t; t.x = acc[g][0]; t.y = acc[g][1];
                qtu2[g*1024 + idx] = t;
            }
        }
        if (tid < G*NHH) {
            const int gg = tid >> 3, n = tid & 7;
            float s = 0.f;
            for (int d = 0; d < 64; d++) s += qs[gg*DD + n*64 + d] * bk[n*64 + d];
            qb[tid] = s;
        }
    }
    __syncthreads();

    // ---- per-batch attention (two passes) ----
    for (int g = 0; g < G; g++) {
        const int b = b0 + g;
        const float4* xb4 = (const float4*)(x_seq + (size_t)b * SS * DD);  // 4096 float4/tile

        // hoist qt lane slices for this warp's 4 heads (pass-1), packed
        u64x2 qtr[4][4];
        #pragma unroll
        for (int h = 0; h < 4; h++)
            #pragma unroll
            for (int m = 0; m < 4; m++)
                qtr[h][m] = qtu2[g*1024 + (hq*4+h)*128 + lane + 32*m];

        // prime tile 0 into buf0
        {
            #pragma unroll
            for (int i = 0; i < 8; i++) cp16(&xs4[tid + 512*i], &xb4[tid + 512*i]);
            cp_commit();
        }

        // ---- pass 1: raw scores (bias added in softmax) ----
        for (int t = 0; t < NT; t++) {
            __syncthreads();   // everyone done with buf[(t+1)&1]'s old contents
            if (t + 1 < NT) {
                float4* dst = xs4 + ((t+1)&1)*4096;
                const float4* src = xb4 + (size_t)(t+1)*4096;
                #pragma unroll
                for (int i = 0; i < 8; i++) cp16(&dst[tid + 512*i], &src[tid + 512*i]);
                cp_commit();
                cp_wait<1>();
            } else {
                cp_wait<0>();
            }
            __syncthreads();   // tile t visible to all

            const float* buf = xs + (t&1)*BUF_F;
            const int base = sl1*4;
            const u64x2* xr0 = (const u64x2*)(buf + (base+0)*DD);
            const u64x2* xr1 = (const u64x2*)(buf + (base+1)*DD);
            const u64x2* xr2 = (const u64x2*)(buf + (base+2)*DD);
            const u64x2* xr3 = (const u64x2*)(buf + (base+3)*DD);

            u64 acc[4][4];   // [h][r]
            #pragma unroll
            for (int h = 0; h < 4; h++)
                #pragma unroll
                for (int r = 0; r < 4; r++) acc[h][r] = 0ull;

            #pragma unroll
            for (int m = 0; m < 4; m++) {
                u64x2 x0 = xr0[lane + 32*m];
                u64x2 x1 = xr1[lane + 32*m];
                u64x2 x2 = xr2[lane + 32*m];
                u64x2 x3 = xr3[lane + 32*m];
                #pragma unroll
                for (int h = 0; h < 4; h++) {
                    acc[h][0] = ffma2(x0.x, qtr[h][m].x, acc[h][0]);
                    acc[h][0] = ffma2(x0.y, qtr[h][m].y, acc[h][0]);
                    acc[h][1] = ffma2(x1.x, qtr[h][m].x, acc[h][1]);
                    acc[h][1] = ffma2(x1.y, qtr[h][m].y, acc[h][1]);
                    acc[h][2] = ffma2(x2.x, qtr[h][m].x, acc[h][2]);
                    acc[h][2] = ffma2(x2.y, qtr[h][m].y, acc[h][2]);
                    acc[h][3] = ffma2(x3.x, qtr[h][m].x, acc[h][3]);
                    acc[h][3] = ffma2(x3.y, qtr[h][m].y, acc[h][3]);
                }
            }
            float vA = reduce8(hsum2(acc[0][0]), hsum2(acc[1][0]), hsum2(acc[2][0]), hsum2(acc[3][0]),
                               hsum2(acc[0][1]), hsum2(acc[1][1]), hsum2(acc[2][1]), hsum2(acc[3][1]),
                               lane);
            float vB = reduce8(hsum2(acc[0][2]), hsum2(acc[1][2]), hsum2(acc[2][2]), hsum2(acc[3][2]),
                               hsum2(acc[0][3]), hsum2(acc[1][3]), hsum2(acc[2][3]), hsum2(acc[3][3]),
                               lane);
            if (lane < 8) {
                const int h = lane & 3;
                const int r = (lane >> 2) & 1;
                float* scp = sc + g*1024 + (hq*4 + h)*SS + t*TS + base;
                scp[r]     = vA;
                scp[2 + r] = vB;
            }
        }
        __syncthreads();

        // ---- softmax (warps 0..7, warp w -> head w); writes packed attn to sc2[s][h] ----
        if (w < NHH) {
            const int* mrow = mask + ((size_t)b*NHH + w)*SS;
            const float qbb = qb[g*NHH + w];
            float l[4];
            #pragma unroll
            for (int k = 0; k < 4; k++) {
                const int s = lane + 32*k;
                float raw = sc[g*1024 + w*SS + s] + qbb;
                l[k] = (mrow[s] != 0) ? floorf(raw * 0.125f) : -1e30f;
            }
            float mx = fmaxf(fmaxf(l[0],l[1]), fmaxf(l[2],l[3]));
            mx = warp_max(mx);
            float e[4]; float ssum = 0.f;
            #pragma unroll
            for (int k = 0; k < 4; k++) { e[k] = __expf(l[k] - mx); ssum += e[k]; }
            ssum = warp_sum(ssum);
            const float inv = 1.0f / ssum;
            #pragma unroll
            for (int k = 0; k < 4; k++) {
                const float v = e[k] * inv;
                sc2[(lane + 32*k)*NHH + w] = pack2(v, v);
            }
        }
        __syncthreads();

        // ---- pass 2: 1x-amplification (cs, rs) mapping; all 8 heads per warp ----
        {
            u64 acc[8][2];   // [head][u64 pair] -> 4 floats of this lane's column slice
            #pragma unroll
            for (int h = 0; h < 8; h++) { acc[h][0] = 0ull; acc[h][1] = 0ull; }

            for (int t = NT-1; t >= 0; t--) {
                if (t <= NT-3) {              // prefetched tile: wait for it
                    if (t > 0) cp_wait<1>(); else cp_wait<0>();
                    __syncthreads();
                }
                const float* buf = xs + (t&1)*BUF_F;
                #pragma unroll
                for (int r = 0; r < 8; r++) {
                    const int srow = rs*8 + r;
                    const int sg   = t*TS + srow;
                    const u64x2* wv4 = (const u64x2*)(sc2 + sg*NHH);
                    u64x2 w01 = wv4[0];
                    u64x2 w23 = wv4[1];
                    u64x2 w45 = wv4[2];
                    u64x2 w67 = wv4[3];
                    u64x2 xv = ((const u64x2*)(buf + srow*DD + cs*128))[lane];
                    acc[0][0] = ffma2(w01.x, xv.x, acc[0][0]);
                    acc[0][1] = ffma2(w01.x, xv.y, acc[0][1]);
                    acc[1][0] = ffma2(w01.y, xv.x, acc[1][0]);
                    acc[1][1] = ffma2(w01.y, xv.y, acc[1][1]);
                    acc[2][0] = ffma2(w23.x, xv.x, acc[2][0]);
                    acc[2][1] = ffma2(w23.x, xv.y, acc[2][1]);
                    acc[3][0] = ffma2(w23.y, xv.x, acc[3][0]);
                    acc[3][1] = ffma2(w23.y, xv.y, acc[3][1]);
                    acc[4][0] = ffma2(w45.x, xv.x, acc[4][0]);
                    acc[4][1] = ffma2(w45.x, xv.y, acc[4][1]);
                    acc[5][0] = ffma2(w45.y, xv.x, acc[5][0]);
                    acc[5][1] = ffma2(w45.y, xv.y, acc[5][1]);
                    acc[6][0] = ffma2(w67.x, xv.x, acc[6][0]);
                    acc[6][1] = ffma2(w67.x, xv.y, acc[6][1]);
                    acc[7][0] = ffma2(w67.y, xv.x, acc[7][0]);
                    acc[7][1] = ffma2(w67.y, xv.y, acc[7][1]);
                }
                __syncthreads();    // done reading buf[t&1]
                if (t - 2 >= 0) {   // prefetch tile t-2 into the buffer just freed
                    float4* dst = xs4 + (t&1)*4096;
                    const float4* src = xb4 + (size_t)(t-2)*4096;
                    #pragma unroll
                    for (int i = 0; i < 8; i++) cp16(&dst[tid + 512*i], &src[tid + 512*i]);
                    cp_commit();
                }
            }

            // dump partials into xs scratch: [rs][head][512 cols], this warp fills its cs slice
            u64x2* xs2 = (u64x2*)xs;
            #pragma unroll
            for (int h = 0; h < 8; h++) {
                u64x2 t0; t0.x = acc[h][0]; t0.y = acc[h][1];
                xs2[(rs*8 + h)*128 + cs*32 + lane] = t0;
            }
            __syncthreads();
            // reduce across the 4 row-slices -> u in qtu[g]
            for (int idx = tid; idx < NHH*128; idx += THREADS) {
                float4 s0 = xs4[0*1024 + idx];
                float4 s1 = xs4[1*1024 + idx];
                float4 s2 = xs4[2*1024 + idx];
                float4 s3 = xs4[3*1024 + idx];
                float4 r;
                r.x = (s0.x + s1.x) + (s2.x + s3.x);
                r.y = (s0.y + s1.y) + (s2.y + s3.y);
                r.z = (s0.z + s1.z) + (s2.z + s3.z);
                r.w = (s0.w + s1.w) + (s2.w + s3.w);
                qtu4[g*1024 + idx] = r;
            }
            __syncthreads();   // scratch consumed before next batch's priming
        }
    } // batches

    // ---- phase z: out[b_g][i] = Wv[i,:]·u[g][head(i)] + bv[i]  (4 rows per iter) ----
    {
        const int zn = w >> 1;   // head for this warp's rows
        u64x2 ur[G][4];
        #pragma unroll
        for (int g = 0; g < G; g++)
            #pragma unroll
            for (int m = 0; m < 4; m++)
                ur[g][m] = qtu2[g*1024 + zn*128 + lane + 32*m];

        for (int rr = 0; rr < 32; rr += 4) {
            const int i = w*32 + rr;
            u64 acc[4][G];
            #pragma unroll
            for (int r = 0; r < 4; r++)
                #pragma unroll
                for (int g = 0; g < G; g++) acc[r][g] = 0ull;
            #pragma unroll
            for (int m = 0; m < 4; m++) {
                #pragma unroll
                for (int r = 0; r < 4; r++) {
                    u64x2 wv = ((const u64x2*)(Wv + (size_t)(i+r)*DD))[lane + 32*m];
                    #pragma unroll
                    for (int g = 0; g < G; g++) {
                        acc[r][g] = ffma2(wv.x, ur[g][m].x, acc[r][g]);
                        acc[r][g] = ffma2(wv.y, ur[g][m].y, acc[r][g]);
                    }
                }
            }
            float vA = reduce8(hsum2(acc[0][0]), hsum2(acc[0][1]), hsum2(acc[0][2]), hsum2(acc[0][3]),
                               hsum2(acc[1][0]), hsum2(acc[1][1]), hsum2(acc[1][2]), hsum2(acc[1][3]),
                               lane);
            float vB = reduce8(hsum2(acc[2][0]), hsum2(acc[2][1]), hsum2(acc[2][2]), hsum2(acc[2][3]),
                               hsum2(acc[3][0]), hsum2(acc[3][1]), hsum2(acc[3][2]), hsum2(acc[3][3]),
                               lane);
            if (lane < 8) {
                const int g  = lane & 3;
                const int r  = (lane >> 2) & 1;
                const int iA = i + r;
                const int iB = i + 2 + r;
                out[(size_t)(b0 + g)*DD + iA] = vA + __ldg(bv + iA);
                out[(size_t)(b0 + g)*DD + iB] = vB + __ldg(bv + iB);
            }
        }
    }
}

extern "C" void kernel_launch(void* const* d_in, const int* in_sizes, int n_in,
                              void* d_out, int out_size)
{
    const float* x_non = (const float*)d_in[0];
    const float* x_seq = (const float*)d_in[1];
    const int*   mask  = (const int*)  d_in[2];
    const float* Wq    = (const float*)d_in[3];
    const float* bq    = (const float*)d_in[4];
    const float* Wk    = (const float*)d_in[5];
    const float* bk    = (const float*)d_in[6];
    const float* Wv    = (const float*)d_in[7];
    const float* bv    = (const float*)d_in[8];
    float* out = (float*)d_out;

    const int smem_bytes = SMEM_F * (int)sizeof(float);   // ~229.5 KB
    cudaFuncSetAttribute(mha_kernel, cudaFuncAttributeMaxDynamicSharedMemorySize, smem_bytes);
    mha_kernel<<<1024/G, THREADS, smem_bytes>>>(x_non, x_seq, mask,
                                                Wq, bq, Wk, bk, Wv, bv, out);
}